// round 2
// baseline (speedup 1.0000x reference)
#include <cuda_runtime.h>
#include <math.h>

typedef unsigned long long u64;

#define BN 4
#define HN 128
#define WN 128
#define CN 768
#define WFQ 65
#define ROWST (WFQ*CN)              /* 49920 u64 per (b,h) row */
#define NELEM (BN*HN*WFQ*CN)        /* 25,559,040 complex */

// Scratch complex buffers (re = low 32 bits, im = high 32 bits)
__device__ __align__(128) u64 g_A[NELEM];
__device__ __align__(128) u64 g_B[NELEM];
// Twiddle tables (128th roots of unity)
__device__ __align__(16) u64 g_tw1[128];   // (c/128, -s/128)           rfft-W fwd
__device__ __align__(16) u64 g_twF[256];   // pairs (c,c),(s,-s)         fwd DFT-H
__device__ __align__(16) u64 g_twI[256];   // pairs (c,c),(-s,s)         inv DFT-H
__device__ __align__(16) u64 g_tw5[256];   // pairs (c,c),(-s,-s)        irfft-W

__device__ __forceinline__ u64 pk2(float lo, float hi){
    u64 r; asm("mov.b64 %0,{%1,%2};":"=l"(r):"f"(lo),"f"(hi)); return r;
}
__device__ __forceinline__ void upk2(u64 v, float& lo, float& hi){
    asm("mov.b64 {%0,%1},%2;":"=f"(lo),"=f"(hi):"l"(v));
}
__device__ __forceinline__ u64 fma2(u64 a, u64 b, u64 c){
    u64 d; asm("fma.rn.f32x2 %0,%1,%2,%3;":"=l"(d):"l"(a),"l"(b),"l"(c)); return d;
}
__device__ __forceinline__ u64 swp2(u64 v){
    float lo,hi; upk2(v,lo,hi); return pk2(hi,lo);
}
__device__ __forceinline__ float sshrink(float v){
    return copysignf(fmaxf(fabsf(v)-0.01f,0.0f), v);
}

// ---------------------------------------------------------------------------
__global__ void k_init(){
    int j = threadIdx.x;                 // 128 threads
    double a = (double)j * (3.14159265358979323846/64.0);
    float c = (float)cos(a), s = (float)sin(a);
    g_tw1[j]     = pk2(c*(1.0f/128.0f), -s*(1.0f/128.0f));
    g_twF[2*j]   = pk2(c,c);  g_twF[2*j+1] = pk2(s,-s);
    g_twI[2*j]   = pk2(c,c);  g_twI[2*j+1] = pk2(-s,s);
    g_tw5[2*j]   = pk2(c,c);  g_tw5[2*j+1] = pk2(-s,-s);
}

// ---------------------------------------------------------------------------
// Stage 1: rfft along W.  x[B,H,W,C] -> g_A[B,H,65,C] (scaled 1/128)
// grid (B*H=512, 6 c-tiles of 128), 256 thr = 32 c-quads x 8 wf-groups(9)
__global__ void __launch_bounds__(256) k_rfftw(const float* __restrict__ x){
    extern __shared__ __align__(16) char smraw[];
    float* xs = (float*)smraw;                 // [128 w][128 c]
    u64*  tws = (u64*)(smraw + 65536);         // 128
    int tid = threadIdx.x;
    int bh = blockIdx.x, cb = blockIdx.y*128;
    const float* xin = x + (size_t)bh*(WN*CN) + cb;
    for(int i=tid;i<16384;i+=256){ int w=i>>7, c=i&127; xs[i]=xin[(size_t)w*CN+c]; }
    if(tid<128) tws[tid]=g_tw1[tid];
    __syncthreads();

    int tc = tid&31, tg = tid>>5;
    int wf0 = tg*9;
    u64 acc[9][4];
    int idx[9];
    #pragma unroll
    for(int j=0;j<9;j++){ idx[j]=0;
        #pragma unroll
        for(int q=0;q<4;q++) acc[j][q]=0ull; }

    for(int w=0;w<128;w++){
        float4 xv = *(const float4*)&xs[w*128 + tc*4];
        u64 x0=pk2(xv.x,xv.x), x1=pk2(xv.y,xv.y), x2=pk2(xv.z,xv.z), x3=pk2(xv.w,xv.w);
        #pragma unroll
        for(int j=0;j<9;j++){
            u64 t = tws[idx[j]];
            acc[j][0]=fma2(x0,t,acc[j][0]);
            acc[j][1]=fma2(x1,t,acc[j][1]);
            acc[j][2]=fma2(x2,t,acc[j][2]);
            acc[j][3]=fma2(x3,t,acc[j][3]);
            idx[j]=(idx[j]+wf0+j)&127;
        }
    }
    u64* ob = g_A + (size_t)bh*ROWST + cb + tc*4;
    #pragma unroll
    for(int j=0;j<9;j++){
        int wf = wf0+j;
        if(wf < WFQ){
            u64* p = ob + (size_t)wf*CN;
            ulonglong2 s0; s0.x=acc[j][0]; s0.y=acc[j][1];
            ulonglong2 s1; s1.x=acc[j][2]; s1.y=acc[j][3];
            *(ulonglong2*)(p)   = s0;
            *(ulonglong2*)(p+2) = s1;
        }
    }
}

// ---------------------------------------------------------------------------
// Stage 2/4: DFT along H. dir=0: fwd g_A->g_B. dir=1: inv g_B->g_A.
// grid (B*65=260, 6 c-tiles), 256 thr = 64 c-pairs x 4 k-groups; 4 chunks x 8 k
__global__ void __launch_bounds__(256) k_ffth(int dir){
    extern __shared__ __align__(16) char smraw[];
    u64* xs  = (u64*)smraw;                    // [128 h][128 c] complex
    u64* tws = (u64*)(smraw + 131072);         // 256 (pairs)
    int tid = threadIdx.x;
    int b = blockIdx.x / WFQ, wf = blockIdx.x % WFQ;
    int cb = blockIdx.y*128;
    const u64* in = dir ? g_B : g_A;
    u64* out      = dir ? g_A : g_B;
    size_t base = (size_t)b*HN*ROWST + (size_t)wf*CN + cb;

    for(int i=tid;i<8192;i+=256){
        int h=i>>6, cp=i&63;
        ulonglong2 v = *(const ulonglong2*)(in + base + (size_t)h*ROWST + cp*2);
        *(ulonglong2*)&xs[h*128 + cp*2] = v;
    }
    tws[tid&255] = dir ? g_twI[tid&255] : g_twF[tid&255];  // tid<256 covers all
    __syncthreads();

    int tc = tid&63, tg = tid>>6;
    for(int cc=0;cc<4;cc++){
        int k0 = cc*32 + tg*8;
        u64 acc[8][2];
        int idx[8];
        #pragma unroll
        for(int j=0;j<8;j++){ idx[j]=0; acc[j][0]=0ull; acc[j][1]=0ull; }
        for(int h=0;h<128;h++){
            ulonglong2 xv = *(const ulonglong2*)&xs[h*128 + tc*2];
            u64 x0=xv.x, x1=xv.y, s0=swp2(x0), s1=swp2(x1);
            #pragma unroll
            for(int j=0;j<8;j++){
                ulonglong2 tw = *(const ulonglong2*)&tws[2*idx[j]];
                acc[j][0]=fma2(x0,tw.x,acc[j][0]);
                acc[j][0]=fma2(s0,tw.y,acc[j][0]);
                acc[j][1]=fma2(x1,tw.x,acc[j][1]);
                acc[j][1]=fma2(s1,tw.y,acc[j][1]);
                idx[j]=(idx[j]+k0+j)&127;
            }
        }
        #pragma unroll
        for(int j=0;j<8;j++){
            int k = k0+j;
            ulonglong2 s; s.x=acc[j][0]; s.y=acc[j][1];
            *(ulonglong2*)(out + base + (size_t)k*ROWST + tc*2) = s;
        }
    }
}

// ---------------------------------------------------------------------------
// Stage 3: one complex block-diagonal MLP layer with softshrink.
// grid (260 point-tiles of 128, 8 blocks kb). 256 thr = 64 point-pairs x 4 o-groups(24).
// smem: ws float2[96*96] | bs float2[96] | xs u64 [96 i][130] (reused as out [128 p][97])
__global__ void __launch_bounds__(256) k_mlp(int which, const float* __restrict__ w,
                                             const float* __restrict__ bvec){
    extern __shared__ __align__(16) char smraw[];
    float2* ws = (float2*)smraw;                    // 73728 B
    float2* bs = (float2*)(smraw + 73728);          // 768 B
    u64* xs    = (u64*)(smraw + 74496);             // 99840 B
    int tid = threadIdx.x;
    int P0 = blockIdx.x*128, kb = blockIdx.y;
    const u64* in = which ? g_A : g_B;
    u64* out      = which ? g_B : g_A;

    for(int t=tid;t<9216;t+=256){
        float wr = w[(size_t)kb*9216 + t];
        float wi = w[(size_t)(8+kb)*9216 + t];
        ws[t] = make_float2(wr, wi);
    }
    if(tid<96) bs[tid] = make_float2(bvec[kb*96+tid], bvec[(8+kb)*96+tid]);
    for(int t=tid;t<12288;t+=256){
        int p = t/96, i = t - p*96;
        xs[i*130 + p] = in[(size_t)(P0+p)*CN + kb*96 + i];
    }
    __syncthreads();

    int pp = tid&63, og = tid>>6;
    int p0 = 2*pp, o0 = og*24;
    u64 are[24], aim[24];
    #pragma unroll
    for(int j=0;j<24;j++){
        float2 bb = bs[o0+j];
        are[j]=pk2(bb.x,bb.x); aim[j]=pk2(bb.y,bb.y);
    }
    for(int i=0;i<96;i++){
        ulonglong2 xv = *(const ulonglong2*)&xs[i*130 + p0];
        float xr0,xi0,xr1,xi1;
        upk2(xv.x,xr0,xi0); upk2(xv.y,xr1,xi1);
        u64 rr = pk2(xr0,xr1), ii = pk2(xi0,xi1), nii = pk2(-xi0,-xi1);
        const float4* wrow = (const float4*)&ws[i*96 + o0];
        #pragma unroll
        for(int j=0;j<24;j+=2){
            float4 wv = wrow[j>>1];
            u64 pw0=pk2(wv.x,wv.x), pv0=pk2(wv.y,wv.y);
            u64 pw1=pk2(wv.z,wv.z), pv1=pk2(wv.w,wv.w);
            are[j]  =fma2(rr, pw0,are[j]);   are[j]  =fma2(nii,pv0,are[j]);
            aim[j]  =fma2(ii, pw0,aim[j]);   aim[j]  =fma2(rr, pv0,aim[j]);
            are[j+1]=fma2(rr, pw1,are[j+1]); are[j+1]=fma2(nii,pv1,are[j+1]);
            aim[j+1]=fma2(ii, pw1,aim[j+1]); aim[j+1]=fma2(rr, pv1,aim[j+1]);
        }
    }
    __syncthreads();  // all reads of xs done -> safe to overwrite as staging
    #pragma unroll
    for(int j=0;j<24;j++){
        float re0,re1,im0,im1;
        upk2(are[j],re0,re1); upk2(aim[j],im0,im1);
        re0=sshrink(re0); re1=sshrink(re1); im0=sshrink(im0); im1=sshrink(im1);
        xs[p0*97 + o0 + j]     = pk2(re0,im0);
        xs[(p0+1)*97 + o0 + j] = pk2(re1,im1);
    }
    __syncthreads();
    for(int t=tid;t<12288;t+=256){
        int p = t/96, o = t - p*96;
        out[(size_t)(P0+p)*CN + kb*96 + o] = xs[p*97 + o];
    }
}

// ---------------------------------------------------------------------------
// Stage 5: irfft along W + residual.  g_A[b,h,65,c] -> y[b,h,w,c] = sum + x
// grid (512, 6), 256 thr = 32 c-quads x 8 w-groups(16)
__global__ void __launch_bounds__(256) k_irfftw(const float* __restrict__ x,
                                                float* __restrict__ y){
    extern __shared__ __align__(16) char smraw[];
    u64* xs  = (u64*)smraw;                    // [65 wf][128 c] complex
    u64* tws = (u64*)(smraw + 66560);          // 256 pairs
    int tid = threadIdx.x;
    int bh = blockIdx.x, cb = blockIdx.y*128;
    size_t base = (size_t)bh*ROWST + cb;

    for(int t=tid;t<4160;t+=256){
        int wf=t>>6, cp=t&63;
        float wt = (wf==0 || wf==64) ? (1.0f/128.0f) : (2.0f/128.0f);
        u64 pwt = pk2(wt,wt);
        ulonglong2 v = *(const ulonglong2*)(g_A + base + (size_t)wf*CN + cp*2);
        v.x = fma2(v.x,pwt,0ull); v.y = fma2(v.y,pwt,0ull);
        *(ulonglong2*)&xs[wf*128 + cp*2] = v;
    }
    tws[tid&255] = g_tw5[tid&255];
    __syncthreads();

    int tc = tid&31, tg = tid>>5;
    int w0 = tg*16;
    u64 acc[16][2];
    int idx[16];
    #pragma unroll
    for(int t=0;t<16;t++){ idx[t]=0; acc[t][0]=0ull; acc[t][1]=0ull; }

    for(int wf=0; wf<WFQ; wf++){
        ulonglong2 xa = *(const ulonglong2*)&xs[wf*128 + tc*4];
        ulonglong2 xb = *(const ulonglong2*)&xs[wf*128 + tc*4 + 2];
        float r0,i0,r1,i1,r2,i2,r3,i3;
        upk2(xa.x,r0,i0); upk2(xa.y,r1,i1); upk2(xb.x,r2,i2); upk2(xb.y,r3,i3);
        u64 rrA=pk2(r0,r1), iiA=pk2(i0,i1), rrB=pk2(r2,r3), iiB=pk2(i2,i3);
        #pragma unroll
        for(int t=0;t<16;t++){
            ulonglong2 tw = *(const ulonglong2*)&tws[2*idx[t]];
            acc[t][0]=fma2(rrA,tw.x,acc[t][0]);
            acc[t][0]=fma2(iiA,tw.y,acc[t][0]);
            acc[t][1]=fma2(rrB,tw.x,acc[t][1]);
            acc[t][1]=fma2(iiB,tw.y,acc[t][1]);
            idx[t]=(idx[t]+w0+t)&127;
        }
    }
    size_t obase = (size_t)bh*(WN*CN) + cb + tc*4;
    #pragma unroll
    for(int t=0;t<16;t++){
        int w = w0+t;
        size_t off = obase + (size_t)w*CN;
        float4 bv = *(const float4*)(x + off);
        float y0,y1,y2,y3;
        upk2(acc[t][0],y0,y1); upk2(acc[t][1],y2,y3);
        float4 ov; ov.x=y0+bv.x; ov.y=y1+bv.y; ov.z=y2+bv.z; ov.w=y3+bv.w;
        *(float4*)(y + off) = ov;
    }
}

// ---------------------------------------------------------------------------
extern "C" void kernel_launch(void* const* d_in, const int* in_sizes, int n_in,
                              void* d_out, int out_size) {
    const float* x  = (const float*)d_in[0];
    const float* w1 = (const float*)d_in[1];
    const float* w2 = (const float*)d_in[2];
    const float* b1 = (const float*)d_in[3];
    const float* b2 = (const float*)d_in[4];
    float* y = (float*)d_out;

    cudaFuncSetAttribute(k_rfftw,  cudaFuncAttributeMaxDynamicSharedMemorySize, 66560);
    cudaFuncSetAttribute(k_ffth,   cudaFuncAttributeMaxDynamicSharedMemorySize, 133120);
    cudaFuncSetAttribute(k_mlp,    cudaFuncAttributeMaxDynamicSharedMemorySize, 174336);
    cudaFuncSetAttribute(k_irfftw, cudaFuncAttributeMaxDynamicSharedMemorySize, 68608);

    k_init<<<1,128>>>();
    k_rfftw<<<dim3(512,6),256,66560>>>(x);
    k_ffth<<<dim3(260,6),256,133120>>>(0);
    k_mlp<<<dim3(260,8),256,174336>>>(0, w1, b1);
    k_mlp<<<dim3(260,8),256,174336>>>(1, w2, b2);
    k_ffth<<<dim3(260,6),256,133120>>>(1);
    k_irfftw<<<dim3(512,6),256,68608>>>(x, y);
    (void)in_sizes; (void)n_in; (void)out_size;
}

// round 3
// speedup vs baseline: 2.0626x; 2.0626x over previous
#include <cuda_runtime.h>
#include <math.h>

typedef unsigned long long u64;

#define BN 4
#define HN 128
#define WN 128
#define CN 768
#define WFQ 65
#define ROWST (WFQ*CN)              /* 49920 u64 per (b,h) row */
#define NELEM (BN*HN*WFQ*CN)        /* 25,559,040 complex */

// Scratch complex buffers (re = low 32 bits, im = high 32 bits)
__device__ __align__(128) u64 g_A[NELEM];
__device__ __align__(128) u64 g_B[NELEM];
// Twiddle tables (128th roots of unity), cmul-ready pairs
__device__ __align__(16) u64 g_twF[256];   // pairs (c,c),(s,-s)   fwd  e^{-i}
__device__ __align__(16) u64 g_twI[256];   // pairs (c,c),(-s,s)   inv  e^{+i}

__device__ __forceinline__ u64 pk2(float lo, float hi){
    u64 r; asm("mov.b64 %0,{%1,%2};":"=l"(r):"f"(lo),"f"(hi)); return r;
}
__device__ __forceinline__ void upk2(u64 v, float& lo, float& hi){
    asm("mov.b64 {%0,%1},%2;":"=f"(lo),"=f"(hi):"l"(v));
}
__device__ __forceinline__ u64 fma2(u64 a, u64 b, u64 c){
    u64 d; asm("fma.rn.f32x2 %0,%1,%2,%3;":"=l"(d):"l"(a),"l"(b),"l"(c)); return d;
}
__device__ __forceinline__ u64 mul2(u64 a, u64 b){
    u64 d; asm("mul.rn.f32x2 %0,%1,%2;":"=l"(d):"l"(a),"l"(b)); return d;
}
__device__ __forceinline__ u64 add2(u64 a, u64 b){
    u64 d; asm("add.rn.f32x2 %0,%1,%2;":"=l"(d):"l"(a),"l"(b)); return d;
}
__device__ __forceinline__ u64 swp2(u64 v){
    float lo,hi; upk2(v,lo,hi); return pk2(hi,lo);
}
__device__ __forceinline__ float sshrink(float v){
    return copysignf(fmaxf(fabsf(v)-0.01f,0.0f), v);
}

// ---------------------------------------------------------------------------
__global__ void k_init(){
    int j = threadIdx.x;                 // 128 threads
    double a = (double)j * (3.14159265358979323846/64.0);
    float c = (float)cos(a), s = (float)sin(a);
    g_twF[2*j]   = pk2(c,c);  g_twF[2*j+1] = pk2(s,-s);
    g_twI[2*j]   = pk2(c,c);  g_twI[2*j+1] = pk2(-s,s);
}

// ---------------------------------------------------------------------------
// In-smem 128-point radix-2 DIF FFT over xs[128 pts][64 cols] (u64 packed
// complex). 256 threads: c = tid&63, tg = tid>>6 (4 groups x 16 butterflies).
// On exit, slot i holds X[bitrev7(i)]. Caller syncs are inside.
__device__ __forceinline__ void fft128(u64* xs, const ulonglong2* tws,
                                       int c, int tg){
    const u64 NEG1 = 0xBF800000BF800000ULL; // (-1.f,-1.f)
    #pragma unroll 1
    for(int lm=6; lm>=0; lm--){
        int m = 1<<lm;
        #pragma unroll
        for(int u=0; u<16; u++){
            int t = tg*16+u;
            int j = t & (m-1);
            int i1 = ((t>>lm)<<(lm+1)) + j;
            int i2 = i1 + m;
            u64 a = xs[i1*64+c], b = xs[i2*64+c];
            u64 sum = add2(a,b);
            u64 dif = fma2(b, NEG1, a);
            ulonglong2 w = tws[j<<(6-lm)];
            u64 res = fma2(swp2(dif), w.y, mul2(dif, w.x));
            xs[i1*64+c] = sum;
            xs[i2*64+c] = res;
        }
        __syncthreads();
    }
}

#define FFT_SMEM (65536 + 1024)

// ---------------------------------------------------------------------------
// Stage 1: rfft along W, two real channels packed per complex FFT.
// grid (B*H=512, 6 tiles of 128 channels), 256 thr.
// out: g_A[b,h,k,c] = X[k] scaled by 1/128 (full fwd ortho factor), k<65.
__global__ void __launch_bounds__(256) k_s1(const float* __restrict__ x){
    extern __shared__ __align__(16) char smraw[];
    u64* xs = (u64*)smraw;                       // [128][64]
    ulonglong2* tws = (ulonglong2*)(smraw + 65536);
    int tid = threadIdx.x, c = tid&63, tg = tid>>6;
    int bh = blockIdx.x, cb = blockIdx.y*128;
    const float* xin = x + (size_t)bh*(WN*CN) + cb;
    for(int i=tid;i<8192;i+=256){
        int w=i>>6, cc=i&63;
        float2 v = *(const float2*)&xin[(size_t)w*CN + 2*cc];
        xs[i] = pk2(v.x, v.y);
    }
    if(tid<64) tws[tid] = *(const ulonglong2*)&g_twF[2*tid];
    __syncthreads();
    fft128(xs, tws, c, tg);

    // unscramble: Xc = (Z[k]+conj(Z[-k]))/2 ; Xd = -i(Z[k]-conj(Z[-k]))/2
    u64* ob = g_A + (size_t)bh*ROWST + cb;
    const float sc = 1.0f/256.0f;   // 0.5 * (1/128 ortho)
    for(int k=tg; k<65; k+=4){
        int s1 = __brev(k)>>25;
        int s2 = __brev((128-k)&127)>>25;
        u64 Z = xs[s1*64+c], Zm = xs[s2*64+c];
        float a,b,p,q; upk2(Z,a,b); upk2(Zm,p,q);
        ulonglong2 st;
        st.x = pk2(sc*(a+p), sc*(b-q));
        st.y = pk2(sc*(b+q), sc*(p-a));
        *(ulonglong2*)&ob[(size_t)k*CN + 2*c] = st;
    }
}

// ---------------------------------------------------------------------------
// Stage 2/4: complex FFT along H. dir=0: fwd g_A->g_B. dir=1: inv g_B->g_A.
// grid (B*65=260, 12 tiles of 64 channels), 256 thr.
__global__ void __launch_bounds__(256) k_ffth(int dir){
    extern __shared__ __align__(16) char smraw[];
    u64* xs = (u64*)smraw;
    ulonglong2* tws = (ulonglong2*)(smraw + 65536);
    int tid = threadIdx.x, c = tid&63, tg = tid>>6;
    int b = blockIdx.x / WFQ, wf = blockIdx.x % WFQ;
    int cb = blockIdx.y*64;
    const u64* in = dir ? g_B : g_A;
    u64* out      = dir ? g_A : g_B;
    size_t base = (size_t)b*HN*ROWST + (size_t)wf*CN + cb;

    for(int i=tid;i<4096;i+=256){
        int h=i>>5, cp=i&31;
        ulonglong2 v = *(const ulonglong2*)(in + base + (size_t)h*ROWST + 2*cp);
        *(ulonglong2*)&xs[h*64 + 2*cp] = v;
    }
    if(tid<64) tws[tid] = *(const ulonglong2*)(dir ? &g_twI[2*tid] : &g_twF[2*tid]);
    __syncthreads();
    fft128(xs, tws, c, tg);

    for(int s=tid;s<4096;s+=256){
        int islot=s>>5, cp=s&31;
        int k = __brev(islot)>>25;
        ulonglong2 v = *(const ulonglong2*)&xs[islot*64 + 2*cp];
        *(ulonglong2*)(out + base + (size_t)k*ROWST + 2*cp) = v;
    }
}

// ---------------------------------------------------------------------------
// Stage 3: one complex block-diagonal MLP layer with softshrink (unchanged).
__global__ void __launch_bounds__(256) k_mlp(int which, const float* __restrict__ w,
                                             const float* __restrict__ bvec){
    extern __shared__ __align__(16) char smraw[];
    float2* ws = (float2*)smraw;                    // 73728 B
    float2* bs = (float2*)(smraw + 73728);          // 768 B
    u64* xs    = (u64*)(smraw + 74496);             // 99840 B
    int tid = threadIdx.x;
    int P0 = blockIdx.x*128, kb = blockIdx.y;
    const u64* in = which ? g_A : g_B;
    u64* out      = which ? g_B : g_A;

    for(int t=tid;t<9216;t+=256){
        float wr = w[(size_t)kb*9216 + t];
        float wi = w[(size_t)(8+kb)*9216 + t];
        ws[t] = make_float2(wr, wi);
    }
    if(tid<96) bs[tid] = make_float2(bvec[kb*96+tid], bvec[(8+kb)*96+tid]);
    for(int t=tid;t<12288;t+=256){
        int p = t/96, i = t - p*96;
        xs[i*130 + p] = in[(size_t)(P0+p)*CN + kb*96 + i];
    }
    __syncthreads();

    int pp = tid&63, og = tid>>6;
    int p0 = 2*pp, o0 = og*24;
    u64 are[24], aim[24];
    #pragma unroll
    for(int j=0;j<24;j++){
        float2 bb = bs[o0+j];
        are[j]=pk2(bb.x,bb.x); aim[j]=pk2(bb.y,bb.y);
    }
    for(int i=0;i<96;i++){
        ulonglong2 xv = *(const ulonglong2*)&xs[i*130 + p0];
        float xr0,xi0,xr1,xi1;
        upk2(xv.x,xr0,xi0); upk2(xv.y,xr1,xi1);
        u64 rr = pk2(xr0,xr1), ii = pk2(xi0,xi1), nii = pk2(-xi0,-xi1);
        const float4* wrow = (const float4*)&ws[i*96 + o0];
        #pragma unroll
        for(int j=0;j<24;j+=2){
            float4 wv = wrow[j>>1];
            u64 pw0=pk2(wv.x,wv.x), pv0=pk2(wv.y,wv.y);
            u64 pw1=pk2(wv.z,wv.z), pv1=pk2(wv.w,wv.w);
            are[j]  =fma2(rr, pw0,are[j]);   are[j]  =fma2(nii,pv0,are[j]);
            aim[j]  =fma2(ii, pw0,aim[j]);   aim[j]  =fma2(rr, pv0,aim[j]);
            are[j+1]=fma2(rr, pw1,are[j+1]); are[j+1]=fma2(nii,pv1,are[j+1]);
            aim[j+1]=fma2(ii, pw1,aim[j+1]); aim[j+1]=fma2(rr, pv1,aim[j+1]);
        }
    }
    __syncthreads();  // all reads of xs done -> safe to overwrite as staging
    #pragma unroll
    for(int j=0;j<24;j++){
        float re0,re1,im0,im1;
        upk2(are[j],re0,re1); upk2(aim[j],im0,im1);
        re0=sshrink(re0); re1=sshrink(re1); im0=sshrink(im0); im1=sshrink(im1);
        xs[p0*97 + o0 + j]     = pk2(re0,im0);
        xs[(p0+1)*97 + o0 + j] = pk2(re1,im1);
    }
    __syncthreads();
    for(int t=tid;t<12288;t+=256){
        int p = t/96, o = t - p*96;
        out[(size_t)(P0+p)*CN + kb*96 + o] = xs[p*97 + o];
    }
}

// ---------------------------------------------------------------------------
// Stage 5: irfft along W + residual, two real outputs packed per complex FFT.
// grid (512, 6 tiles of 128 channels), 256 thr.
__global__ void __launch_bounds__(256) k_s5(const float* __restrict__ x,
                                            float* __restrict__ y){
    extern __shared__ __align__(16) char smraw[];
    u64* xs = (u64*)smraw;
    ulonglong2* tws = (ulonglong2*)(smraw + 65536);
    int tid = threadIdx.x, c = tid&63, tg = tid>>6;
    int bh = blockIdx.x, cb = blockIdx.y*128;
    const u64* in = g_A + (size_t)bh*ROWST + cb;
    const float sc = 1.0f/128.0f;   // inverse ortho total

    // Build paired spectrum Z[k] = Xc[k] + i*Xd[k], hermitian-extended.
    // pocketfft C2R ignores Im at DC/Nyquist -> zero them.
    for(int t=tid;t<65*64;t+=256){
        int k=t>>6, cc=t&63;
        ulonglong2 v = *(const ulonglong2*)&in[(size_t)k*CN + 2*cc];
        float cr,ci,dr,di; upk2(v.x,cr,ci); upk2(v.y,dr,di);
        if(k==0 || k==64){ ci = 0.0f; di = 0.0f; }
        xs[k*64+cc] = pk2(sc*(cr-di), sc*(ci+dr));
        if(k>=1 && k<=63)
            xs[(128-k)*64+cc] = pk2(sc*(cr+di), sc*(dr-ci));
    }
    if(tid<64) tws[tid] = *(const ulonglong2*)&g_twI[2*tid];
    __syncthreads();
    fft128(xs, tws, c, tg);   // inverse (e^{+i}), unnormalized

    size_t obase = (size_t)bh*(WN*CN) + cb;
    for(int s=tid;s<8192;s+=256){
        int islot=s>>6, cc=s&63;
        int w = __brev(islot)>>25;
        float yr,yi; upk2(xs[s], yr, yi);
        size_t off = obase + (size_t)w*CN + 2*cc;
        float2 bv = *(const float2*)&x[off];
        *(float2*)&y[off] = make_float2(yr+bv.x, yi+bv.y);
    }
}

// ---------------------------------------------------------------------------
extern "C" void kernel_launch(void* const* d_in, const int* in_sizes, int n_in,
                              void* d_out, int out_size) {
    const float* x  = (const float*)d_in[0];
    const float* w1 = (const float*)d_in[1];
    const float* w2 = (const float*)d_in[2];
    const float* b1 = (const float*)d_in[3];
    const float* b2 = (const float*)d_in[4];
    float* y = (float*)d_out;

    cudaFuncSetAttribute(k_s1,   cudaFuncAttributeMaxDynamicSharedMemorySize, FFT_SMEM);
    cudaFuncSetAttribute(k_ffth, cudaFuncAttributeMaxDynamicSharedMemorySize, FFT_SMEM);
    cudaFuncSetAttribute(k_s5,   cudaFuncAttributeMaxDynamicSharedMemorySize, FFT_SMEM);
    cudaFuncSetAttribute(k_mlp,  cudaFuncAttributeMaxDynamicSharedMemorySize, 174336);

    k_init<<<1,128>>>();
    k_s1  <<<dim3(512,6), 256, FFT_SMEM>>>(x);
    k_ffth<<<dim3(260,12),256, FFT_SMEM>>>(0);
    k_mlp <<<dim3(260,8), 256, 174336>>>(0, w1, b1);
    k_mlp <<<dim3(260,8), 256, 174336>>>(1, w2, b2);
    k_ffth<<<dim3(260,12),256, FFT_SMEM>>>(1);
    k_s5  <<<dim3(512,6), 256, FFT_SMEM>>>(x, y);
    (void)in_sizes; (void)n_in; (void)out_size;
}

// round 4
// speedup vs baseline: 2.2495x; 1.0906x over previous
#include <cuda_runtime.h>
#include <math.h>

typedef unsigned long long u64;

#define BN 4
#define HN 128
#define WN 128
#define CN 768
#define WFQ 65
#define ROWST (WFQ*CN)              /* 49920 u64 per (b,h) row */
#define NELEM (BN*HN*WFQ*CN)        /* 25,559,040 complex */

// Scratch complex buffers (re = low 32 bits, im = high 32 bits)
__device__ __align__(128) u64 g_A[NELEM];
__device__ __align__(128) u64 g_B[NELEM];
// Twiddle tables (128th roots of unity), cmul-ready pairs
__device__ __align__(16) u64 g_twF[256];   // pairs (c,c),(s,-s)   fwd  e^{-i}
__device__ __align__(16) u64 g_twI[256];   // pairs (c,c),(-s,s)   inv  e^{+i}

__device__ __forceinline__ u64 pk2(float lo, float hi){
    u64 r; asm("mov.b64 %0,{%1,%2};":"=l"(r):"f"(lo),"f"(hi)); return r;
}
__device__ __forceinline__ void upk2(u64 v, float& lo, float& hi){
    asm("mov.b64 {%0,%1},%2;":"=f"(lo),"=f"(hi):"l"(v));
}
__device__ __forceinline__ u64 fma2(u64 a, u64 b, u64 c){
    u64 d; asm("fma.rn.f32x2 %0,%1,%2,%3;":"=l"(d):"l"(a),"l"(b),"l"(c)); return d;
}
__device__ __forceinline__ u64 mul2(u64 a, u64 b){
    u64 d; asm("mul.rn.f32x2 %0,%1,%2;":"=l"(d):"l"(a),"l"(b)); return d;
}
__device__ __forceinline__ u64 add2(u64 a, u64 b){
    u64 d; asm("add.rn.f32x2 %0,%1,%2;":"=l"(d):"l"(a),"l"(b)); return d;
}
__device__ __forceinline__ u64 swp2(u64 v){
    float lo,hi; upk2(v,lo,hi); return pk2(hi,lo);
}
__device__ __forceinline__ float sshrink(float v){
    return copysignf(fmaxf(fabsf(v)-0.01f,0.0f), v);
}

// ---------------------------------------------------------------------------
__global__ void k_init(){
    int j = threadIdx.x;                 // 128 threads
    double a = (double)j * (3.14159265358979323846/64.0);
    float c = (float)cos(a), s = (float)sin(a);
    g_twF[2*j]   = pk2(c,c);  g_twF[2*j+1] = pk2(s,-s);
    g_twI[2*j]   = pk2(c,c);  g_twI[2*j+1] = pk2(-s,s);
}

// ---------------------------------------------------------------------------
// In-smem 128-point radix-2 DIF FFT over xs[128 pts][64 cols] (u64 packed
// complex). 256 threads: c = tid&63, tg = tid>>6 (4 groups x 16 butterflies).
// On exit, slot i holds X[bitrev7(i)]. Caller syncs are inside.
__device__ __forceinline__ void fft128(u64* xs, const ulonglong2* tws,
                                       int c, int tg){
    const u64 NEG1 = 0xBF800000BF800000ULL; // (-1.f,-1.f)
    #pragma unroll 1
    for(int lm=6; lm>=0; lm--){
        int m = 1<<lm;
        #pragma unroll
        for(int u=0; u<16; u++){
            int t = tg*16+u;
            int j = t & (m-1);
            int i1 = ((t>>lm)<<(lm+1)) + j;
            int i2 = i1 + m;
            u64 a = xs[i1*64+c], b = xs[i2*64+c];
            u64 sum = add2(a,b);
            u64 dif = fma2(b, NEG1, a);
            ulonglong2 w = tws[j<<(6-lm)];
            u64 res = fma2(swp2(dif), w.y, mul2(dif, w.x));
            xs[i1*64+c] = sum;
            xs[i2*64+c] = res;
        }
        __syncthreads();
    }
}

#define FFT_SMEM (65536 + 1024)

// ---------------------------------------------------------------------------
// Stage 1: rfft along W, two real channels packed per complex FFT.
// grid (B*H=512, 6 tiles of 128 channels), 256 thr.
// out: g_A[b,h,k,c] = X[k] scaled by 1/128 (full fwd ortho factor), k<65.
__global__ void __launch_bounds__(256) k_s1(const float* __restrict__ x){
    extern __shared__ __align__(16) char smraw[];
    u64* xs = (u64*)smraw;                       // [128][64]
    ulonglong2* tws = (ulonglong2*)(smraw + 65536);
    int tid = threadIdx.x, c = tid&63, tg = tid>>6;
    int bh = blockIdx.x, cb = blockIdx.y*128;
    const float* xin = x + (size_t)bh*(WN*CN) + cb;
    for(int i=tid;i<8192;i+=256){
        int w=i>>6, cc=i&63;
        float2 v = *(const float2*)&xin[(size_t)w*CN + 2*cc];
        xs[i] = pk2(v.x, v.y);
    }
    if(tid<64) tws[tid] = *(const ulonglong2*)&g_twF[2*tid];
    __syncthreads();
    fft128(xs, tws, c, tg);

    // unscramble: Xc = (Z[k]+conj(Z[-k]))/2 ; Xd = -i(Z[k]-conj(Z[-k]))/2
    u64* ob = g_A + (size_t)bh*ROWST + cb;
    const float sc = 1.0f/256.0f;   // 0.5 * (1/128 ortho)
    for(int k=tg; k<65; k+=4){
        int s1 = __brev(k)>>25;
        int s2 = __brev((128-k)&127)>>25;
        u64 Z = xs[s1*64+c], Zm = xs[s2*64+c];
        float a,b,p,q; upk2(Z,a,b); upk2(Zm,p,q);
        ulonglong2 st;
        st.x = pk2(sc*(a+p), sc*(b-q));
        st.y = pk2(sc*(b+q), sc*(p-a));
        *(ulonglong2*)&ob[(size_t)k*CN + 2*c] = st;
    }
}

// ---------------------------------------------------------------------------
// Stage 2/4: complex FFT along H. dir=0: fwd g_A->g_B. dir=1: inv g_B->g_A.
// grid (B*65=260, 12 tiles of 64 channels), 256 thr.
__global__ void __launch_bounds__(256) k_ffth(int dir){
    extern __shared__ __align__(16) char smraw[];
    u64* xs = (u64*)smraw;
    ulonglong2* tws = (ulonglong2*)(smraw + 65536);
    int tid = threadIdx.x, c = tid&63, tg = tid>>6;
    int b = blockIdx.x / WFQ, wf = blockIdx.x % WFQ;
    int cb = blockIdx.y*64;
    const u64* in = dir ? g_B : g_A;
    u64* out      = dir ? g_A : g_B;
    size_t base = (size_t)b*HN*ROWST + (size_t)wf*CN + cb;

    for(int i=tid;i<4096;i+=256){
        int h=i>>5, cp=i&31;
        ulonglong2 v = *(const ulonglong2*)(in + base + (size_t)h*ROWST + 2*cp);
        *(ulonglong2*)&xs[h*64 + 2*cp] = v;
    }
    if(tid<64) tws[tid] = *(const ulonglong2*)(dir ? &g_twI[2*tid] : &g_twF[2*tid]);
    __syncthreads();
    fft128(xs, tws, c, tg);

    for(int s=tid;s<4096;s+=256){
        int islot=s>>5, cp=s&31;
        int k = __brev(islot)>>25;
        ulonglong2 v = *(const ulonglong2*)&xs[islot*64 + 2*cp];
        *(ulonglong2*)(out + base + (size_t)k*ROWST + 2*cp) = v;
    }
}

// ---------------------------------------------------------------------------
// Stage 3: one complex block-diagonal MLP layer with softshrink.
// Accumulators packed over OUTPUT pairs; x splatted; weights in SoA smem
// planes consumed directly as packed f32x2 (no per-weight splats).
// grid (520 point-tiles of 64, 16 = 8 kb x 2 output-halves of 48). 256 thr
// = 64 points x 4 output-subgroups of 12.
// smem: xs u64[96][65] | wr float[96][48] | wi float[96][48] | bias float2[48]
#define MLP_XS    0
#define MLP_WR    49920
#define MLP_WI    68352
#define MLP_BS    86784
#define MLP_SMEM  87296
__global__ void __launch_bounds__(256) k_mlp(int which, const float* __restrict__ w,
                                             const float* __restrict__ bvec){
    extern __shared__ __align__(16) char smraw[];
    u64*    xs   = (u64*)(smraw + MLP_XS);
    float*  wr_s = (float*)(smraw + MLP_WR);
    float*  wi_s = (float*)(smraw + MLP_WI);
    float2* bs   = (float2*)(smraw + MLP_BS);
    int tid = threadIdx.x;
    int P0 = blockIdx.x*64;
    int kb = blockIdx.y & 7, o0 = (blockIdx.y>>3)*48;
    const u64* in = which ? g_A : g_B;
    u64* out      = which ? g_B : g_A;

    // weights: SoA planes, row stride 48 floats (16B-aligned per subgroup)
    for(int t=tid;t<4608;t+=256){
        int i = t/48, oo = t - i*48;
        wr_s[t] = w[(size_t)kb*9216 + i*96 + o0 + oo];
        wi_s[t] = w[(size_t)(8+kb)*9216 + i*96 + o0 + oo];
    }
    if(tid<48) bs[tid] = make_float2(bvec[kb*96 + o0 + tid],
                                     bvec[768 + kb*96 + o0 + tid]);
    // stage x: [i][p] with padded stride 65
    for(int t=tid;t<6144;t+=256){
        int p = t/96, i = t - p*96;
        xs[i*65 + p] = in[(size_t)(P0+p)*CN + kb*96 + i];
    }
    __syncthreads();

    int p = tid&63, og = tid>>6, ob = og*12;
    u64 are[6], aim[6];
    #pragma unroll
    for(int k=0;k<6;k++){
        float2 b0 = bs[ob+2*k], b1 = bs[ob+2*k+1];
        are[k] = pk2(b0.x, b1.x);
        aim[k] = pk2(b0.y, b1.y);
    }
    #pragma unroll 2
    for(int i=0;i<96;i++){
        float xr, xi; upk2(xs[i*65 + p], xr, xi);
        u64 rr = pk2(xr,xr), ii = pk2(xi,xi), nii = pk2(-xi,-xi);
        const ulonglong2* wrp = (const ulonglong2*)&wr_s[i*48 + ob];
        const ulonglong2* wip = (const ulonglong2*)&wi_s[i*48 + ob];
        #pragma unroll
        for(int m=0;m<3;m++){
            ulonglong2 a = wrp[m], b = wip[m];
            are[2*m]   = fma2(rr,  a.x, are[2*m]);
            are[2*m]   = fma2(nii, b.x, are[2*m]);
            aim[2*m]   = fma2(ii,  a.x, aim[2*m]);
            aim[2*m]   = fma2(rr,  b.x, aim[2*m]);
            are[2*m+1] = fma2(rr,  a.y, are[2*m+1]);
            are[2*m+1] = fma2(nii, b.y, are[2*m+1]);
            aim[2*m+1] = fma2(ii,  a.y, aim[2*m+1]);
            aim[2*m+1] = fma2(rr,  b.y, aim[2*m+1]);
        }
    }
    __syncthreads();   // xs reads done -> reuse as output staging [64 p][49]
    u64* os = xs;
    #pragma unroll
    for(int k=0;k<6;k++){
        float r0,r1,i0,i1;
        upk2(are[k], r0, r1);
        upk2(aim[k], i0, i1);
        os[p*49 + ob + 2*k]     = pk2(sshrink(r0), sshrink(i0));
        os[p*49 + ob + 2*k + 1] = pk2(sshrink(r1), sshrink(i1));
    }
    __syncthreads();
    for(int t=tid;t<3072;t+=256){
        int pp = t/48, oo = t - pp*48;
        out[(size_t)(P0+pp)*CN + kb*96 + o0 + oo] = os[pp*49 + oo];
    }
}

// ---------------------------------------------------------------------------
// Stage 5: irfft along W + residual, two real outputs packed per complex FFT.
// grid (512, 6 tiles of 128 channels), 256 thr.
__global__ void __launch_bounds__(256) k_s5(const float* __restrict__ x,
                                            float* __restrict__ y){
    extern __shared__ __align__(16) char smraw[];
    u64* xs = (u64*)smraw;
    ulonglong2* tws = (ulonglong2*)(smraw + 65536);
    int tid = threadIdx.x, c = tid&63, tg = tid>>6;
    int bh = blockIdx.x, cb = blockIdx.y*128;
    const u64* in = g_A + (size_t)bh*ROWST + cb;
    const float sc = 1.0f/128.0f;   // inverse ortho total

    // Build paired spectrum Z[k] = Xc[k] + i*Xd[k], hermitian-extended.
    // pocketfft C2R ignores Im at DC/Nyquist -> zero them.
    for(int t=tid;t<65*64;t+=256){
        int k=t>>6, cc=t&63;
        ulonglong2 v = *(const ulonglong2*)&in[(size_t)k*CN + 2*cc];
        float cr,ci,dr,di; upk2(v.x,cr,ci); upk2(v.y,dr,di);
        if(k==0 || k==64){ ci = 0.0f; di = 0.0f; }
        xs[k*64+cc] = pk2(sc*(cr-di), sc*(ci+dr));
        if(k>=1 && k<=63)
            xs[(128-k)*64+cc] = pk2(sc*(cr+di), sc*(dr-ci));
    }
    if(tid<64) tws[tid] = *(const ulonglong2*)&g_twI[2*tid];
    __syncthreads();
    fft128(xs, tws, c, tg);   // inverse (e^{+i}), unnormalized

    size_t obase = (size_t)bh*(WN*CN) + cb;
    for(int s=tid;s<8192;s+=256){
        int islot=s>>6, cc=s&63;
        int w = __brev(islot)>>25;
        float yr,yi; upk2(xs[s], yr, yi);
        size_t off = obase + (size_t)w*CN + 2*cc;
        float2 bv = *(const float2*)&x[off];
        *(float2*)&y[off] = make_float2(yr+bv.x, yi+bv.y);
    }
}

// ---------------------------------------------------------------------------
extern "C" void kernel_launch(void* const* d_in, const int* in_sizes, int n_in,
                              void* d_out, int out_size) {
    const float* x  = (const float*)d_in[0];
    const float* w1 = (const float*)d_in[1];
    const float* w2 = (const float*)d_in[2];
    const float* b1 = (const float*)d_in[3];
    const float* b2 = (const float*)d_in[4];
    float* y = (float*)d_out;

    cudaFuncSetAttribute(k_s1,   cudaFuncAttributeMaxDynamicSharedMemorySize, FFT_SMEM);
    cudaFuncSetAttribute(k_ffth, cudaFuncAttributeMaxDynamicSharedMemorySize, FFT_SMEM);
    cudaFuncSetAttribute(k_s5,   cudaFuncAttributeMaxDynamicSharedMemorySize, FFT_SMEM);
    cudaFuncSetAttribute(k_mlp,  cudaFuncAttributeMaxDynamicSharedMemorySize, MLP_SMEM);

    k_init<<<1,128>>>();
    k_s1  <<<dim3(512,6), 256, FFT_SMEM>>>(x);
    k_ffth<<<dim3(260,12),256, FFT_SMEM>>>(0);
    k_mlp <<<dim3(520,16),256, MLP_SMEM>>>(0, w1, b1);
    k_mlp <<<dim3(520,16),256, MLP_SMEM>>>(1, w2, b2);
    k_ffth<<<dim3(260,12),256, FFT_SMEM>>>(1);
    k_s5  <<<dim3(512,6), 256, FFT_SMEM>>>(x, y);
    (void)in_sizes; (void)n_in; (void)out_size;
}

// round 5
// speedup vs baseline: 2.3358x; 1.0384x over previous
#include <cuda_runtime.h>
#include <math.h>

typedef unsigned long long u64;

#define BN 4
#define HN 128
#define WN 128
#define CN 768
#define WFQ 65
#define ROWST (WFQ*CN)              /* 49920 u64 per (b,h) row */
#define NELEM (BN*HN*WFQ*CN)        /* 25,559,040 complex */

// Scratch complex buffers (re = low 32 bits, im = high 32 bits)
__device__ __align__(128) u64 g_A[NELEM];
__device__ __align__(128) u64 g_B[NELEM];
// Twiddle tables (128th roots of unity), cmul-ready pairs
__device__ __align__(16) u64 g_twF[256];   // pairs (c,c),(s,-s)   fwd  e^{-i}
__device__ __align__(16) u64 g_twI[256];   // pairs (c,c),(-s,s)   inv  e^{+i}

__device__ __forceinline__ u64 pk2(float lo, float hi){
    u64 r; asm("mov.b64 %0,{%1,%2};":"=l"(r):"f"(lo),"f"(hi)); return r;
}
__device__ __forceinline__ void upk2(u64 v, float& lo, float& hi){
    asm("mov.b64 {%0,%1},%2;":"=f"(lo),"=f"(hi):"l"(v));
}
__device__ __forceinline__ u64 fma2(u64 a, u64 b, u64 c){
    u64 d; asm("fma.rn.f32x2 %0,%1,%2,%3;":"=l"(d):"l"(a),"l"(b),"l"(c)); return d;
}
__device__ __forceinline__ u64 mul2(u64 a, u64 b){
    u64 d; asm("mul.rn.f32x2 %0,%1,%2;":"=l"(d):"l"(a),"l"(b)); return d;
}
__device__ __forceinline__ u64 add2(u64 a, u64 b){
    u64 d; asm("add.rn.f32x2 %0,%1,%2;":"=l"(d):"l"(a),"l"(b)); return d;
}
__device__ __forceinline__ u64 swp2(u64 v){
    float lo,hi; upk2(v,lo,hi); return pk2(hi,lo);
}
__device__ __forceinline__ float sshrink(float v){
    return copysignf(fmaxf(fabsf(v)-0.01f,0.0f), v);
}

// ---------------------------------------------------------------------------
__global__ void k_init(){
    int j = threadIdx.x;                 // 128 threads
    double a = (double)j * (3.14159265358979323846/64.0);
    float c = (float)cos(a), s = (float)sin(a);
    g_twF[2*j]   = pk2(c,c);  g_twF[2*j+1] = pk2(s,-s);
    g_twI[2*j]   = pk2(c,c);  g_twI[2*j+1] = pk2(-s,s);
}

// ---------------------------------------------------------------------------
// In-smem 128-point radix-2 DIF FFT over xs[128 pts][64 cols] (u64 packed
// complex). 256 threads: c = tid&63, tg = tid>>6 (4 groups x 16 butterflies).
// On exit, slot i holds X[bitrev7(i)]. Caller syncs are inside.
__device__ __forceinline__ void fft128(u64* xs, const ulonglong2* tws,
                                       int c, int tg){
    const u64 NEG1 = 0xBF800000BF800000ULL; // (-1.f,-1.f)
    #pragma unroll 1
    for(int lm=6; lm>=0; lm--){
        int m = 1<<lm;
        #pragma unroll
        for(int u=0; u<16; u++){
            int t = tg*16+u;
            int j = t & (m-1);
            int i1 = ((t>>lm)<<(lm+1)) + j;
            int i2 = i1 + m;
            u64 a = xs[i1*64+c], b = xs[i2*64+c];
            u64 sum = add2(a,b);
            u64 dif = fma2(b, NEG1, a);
            ulonglong2 w = tws[j<<(6-lm)];
            u64 res = fma2(swp2(dif), w.y, mul2(dif, w.x));
            xs[i1*64+c] = sum;
            xs[i2*64+c] = res;
        }
        __syncthreads();
    }
}

#define FFT_SMEM (65536 + 1024)

// ---------------------------------------------------------------------------
// Stage 1: rfft along W, two real channels packed per complex FFT.
// grid (B*H=512, 6 tiles of 128 channels), 256 thr.
// out: g_A[b,h,k,c] = X[k] scaled by 1/128 (full fwd ortho factor), k<65.
__global__ void __launch_bounds__(256) k_s1(const float* __restrict__ x){
    extern __shared__ __align__(16) char smraw[];
    u64* xs = (u64*)smraw;                       // [128][64]
    ulonglong2* tws = (ulonglong2*)(smraw + 65536);
    int tid = threadIdx.x, c = tid&63, tg = tid>>6;
    int bh = blockIdx.x, cb = blockIdx.y*128;
    const float* xin = x + (size_t)bh*(WN*CN) + cb;
    for(int i=tid;i<8192;i+=256){
        int w=i>>6, cc=i&63;
        float2 v = *(const float2*)&xin[(size_t)w*CN + 2*cc];
        xs[i] = pk2(v.x, v.y);
    }
    if(tid<64) tws[tid] = *(const ulonglong2*)&g_twF[2*tid];
    __syncthreads();
    fft128(xs, tws, c, tg);

    // unscramble: Xc = (Z[k]+conj(Z[-k]))/2 ; Xd = -i(Z[k]-conj(Z[-k]))/2
    u64* ob = g_A + (size_t)bh*ROWST + cb;
    const float sc = 1.0f/256.0f;   // 0.5 * (1/128 ortho)
    for(int k=tg; k<65; k+=4){
        int s1 = __brev(k)>>25;
        int s2 = __brev((128-k)&127)>>25;
        u64 Z = xs[s1*64+c], Zm = xs[s2*64+c];
        float a,b,p,q; upk2(Z,a,b); upk2(Zm,p,q);
        ulonglong2 st;
        st.x = pk2(sc*(a+p), sc*(b-q));
        st.y = pk2(sc*(b+q), sc*(p-a));
        *(ulonglong2*)&ob[(size_t)k*CN + 2*c] = st;
    }
}

// ---------------------------------------------------------------------------
// Stage 2/4: complex FFT along H. dir=0: fwd g_A->g_B. dir=1: inv g_B->g_A.
// grid (B*65=260, 12 tiles of 64 channels), 256 thr.
__global__ void __launch_bounds__(256) k_ffth(int dir){
    extern __shared__ __align__(16) char smraw[];
    u64* xs = (u64*)smraw;
    ulonglong2* tws = (ulonglong2*)(smraw + 65536);
    int tid = threadIdx.x, c = tid&63, tg = tid>>6;
    int b = blockIdx.x / WFQ, wf = blockIdx.x % WFQ;
    int cb = blockIdx.y*64;
    const u64* in = dir ? g_B : g_A;
    u64* out      = dir ? g_A : g_B;
    size_t base = (size_t)b*HN*ROWST + (size_t)wf*CN + cb;

    for(int i=tid;i<4096;i+=256){
        int h=i>>5, cp=i&31;
        ulonglong2 v = *(const ulonglong2*)(in + base + (size_t)h*ROWST + 2*cp);
        *(ulonglong2*)&xs[h*64 + 2*cp] = v;
    }
    if(tid<64) tws[tid] = *(const ulonglong2*)(dir ? &g_twI[2*tid] : &g_twF[2*tid]);
    __syncthreads();
    fft128(xs, tws, c, tg);

    for(int s=tid;s<4096;s+=256){
        int islot=s>>5, cp=s&31;
        int k = __brev(islot)>>25;
        ulonglong2 v = *(const ulonglong2*)&xs[islot*64 + 2*cp];
        *(ulonglong2*)(out + base + (size_t)k*ROWST + 2*cp) = v;
    }
}

// ---------------------------------------------------------------------------
// Stage 3: one complex block-diagonal MLP layer with softshrink.
// Register-blocked: 4 points x 12 outputs per thread. x streamed directly
// from global (contiguous over i per point); weights broadcast from smem SoA
// planes; no x staging, no output staging.
// grid (130 point-tiles of 256, 16 = 8 kb x 2 output-halves of 48). 256 thr
// = 64 point-lanes x 4 output-subgroups of 12.
#define MLP_WR    0
#define MLP_WI    18432
#define MLP_BS    36864
#define MLP_SMEM  37376
__global__ void __launch_bounds__(256) k_mlp(int which, const float* __restrict__ w,
                                             const float* __restrict__ bvec){
    extern __shared__ __align__(16) char smraw[];
    float*  wr_s = (float*)(smraw + MLP_WR);
    float*  wi_s = (float*)(smraw + MLP_WI);
    float2* bs   = (float2*)(smraw + MLP_BS);
    int tid = threadIdx.x;
    int P0 = blockIdx.x*256;
    int kb = blockIdx.y & 7, o0 = (blockIdx.y>>3)*48;
    const u64* in = which ? g_A : g_B;
    u64* out      = which ? g_B : g_A;

    for(int t=tid;t<4608;t+=256){
        int i = t/48, oo = t - i*48;
        wr_s[t] = w[(size_t)kb*9216 + i*96 + o0 + oo];
        wi_s[t] = w[(size_t)(8+kb)*9216 + i*96 + o0 + oo];
    }
    if(tid<48) bs[tid] = make_float2(bvec[kb*96 + o0 + tid],
                                     bvec[768 + kb*96 + o0 + tid]);
    __syncthreads();

    int pl = tid&63, og = tid>>6, ob = og*12;
    const u64* xb0 = in + (size_t)(P0 + pl*4)*CN + kb*96;

    u64 are[4][6], aim[4][6];
    #pragma unroll
    for(int k=0;k<6;k++){
        float2 b0 = bs[ob+2*k], b1 = bs[ob+2*k+1];
        u64 r = pk2(b0.x,b1.x), m = pk2(b0.y,b1.y);
        #pragma unroll
        for(int t=0;t<4;t++){ are[t][k]=r; aim[t][k]=m; }
    }

    #pragma unroll 1
    for(int i=0;i<96;i+=4){
        ulonglong2 xa[4], xb[4];
        #pragma unroll
        for(int t=0;t<4;t++){
            const u64* p = xb0 + (size_t)t*CN + i;
            xa[t] = *(const ulonglong2*)p;
            xb[t] = *(const ulonglong2*)(p+2);
        }
        #pragma unroll
        for(int ii=0;ii<4;ii++){
            const ulonglong2* wrp = (const ulonglong2*)&wr_s[(i+ii)*48 + ob];
            const ulonglong2* wip = (const ulonglong2*)&wi_s[(i+ii)*48 + ob];
            ulonglong2 wa = wrp[0], wb = wrp[1], wc = wrp[2];
            ulonglong2 va = wip[0], vb = wip[1], vc = wip[2];
            u64 wreg[6]; u64 vreg[6];
            wreg[0]=wa.x; wreg[1]=wa.y; wreg[2]=wb.x; wreg[3]=wb.y; wreg[4]=wc.x; wreg[5]=wc.y;
            vreg[0]=va.x; vreg[1]=va.y; vreg[2]=vb.x; vreg[3]=vb.y; vreg[4]=vc.x; vreg[5]=vc.y;
            #pragma unroll
            for(int t=0;t<4;t++){
                u64 xv = (ii==0) ? xa[t].x : (ii==1) ? xa[t].y
                       : (ii==2) ? xb[t].x : xb[t].y;
                float xr,xi; upk2(xv,xr,xi);
                u64 rr=pk2(xr,xr), iv=pk2(xi,xi), nii=pk2(-xi,-xi);
                #pragma unroll
                for(int k=0;k<6;k++){
                    are[t][k]=fma2(rr, wreg[k],are[t][k]);
                    are[t][k]=fma2(nii,vreg[k],are[t][k]);
                    aim[t][k]=fma2(iv, wreg[k],aim[t][k]);
                    aim[t][k]=fma2(rr, vreg[k],aim[t][k]);
                }
            }
        }
    }

    u64* obp = out + (size_t)(P0 + pl*4)*CN + kb*96 + o0 + ob;
    #pragma unroll
    for(int t=0;t<4;t++){
        u64* op = obp + (size_t)t*CN;
        #pragma unroll
        for(int k=0;k<3;k++){
            float r0,r1,i0,i1,r2,r3,i2,i3;
            upk2(are[t][2*k],  r0,r1); upk2(aim[t][2*k],  i0,i1);
            upk2(are[t][2*k+1],r2,r3); upk2(aim[t][2*k+1],i2,i3);
            ulonglong2 s0, s1;
            s0.x = pk2(sshrink(r0), sshrink(i0));
            s0.y = pk2(sshrink(r1), sshrink(i1));
            s1.x = pk2(sshrink(r2), sshrink(i2));
            s1.y = pk2(sshrink(r3), sshrink(i3));
            *(ulonglong2*)(op + 4*k)     = s0;
            *(ulonglong2*)(op + 4*k + 2) = s1;
        }
    }
}

// ---------------------------------------------------------------------------
// Stage 5: irfft along W + residual, two real outputs packed per complex FFT.
// grid (512, 6 tiles of 128 channels), 256 thr.
__global__ void __launch_bounds__(256) k_s5(const float* __restrict__ x,
                                            float* __restrict__ y){
    extern __shared__ __align__(16) char smraw[];
    u64* xs = (u64*)smraw;
    ulonglong2* tws = (ulonglong2*)(smraw + 65536);
    int tid = threadIdx.x, c = tid&63, tg = tid>>6;
    int bh = blockIdx.x, cb = blockIdx.y*128;
    const u64* in = g_A + (size_t)bh*ROWST + cb;
    const float sc = 1.0f/128.0f;   // inverse ortho total

    // Build paired spectrum Z[k] = Xc[k] + i*Xd[k], hermitian-extended.
    // pocketfft C2R ignores Im at DC/Nyquist -> zero them.
    for(int t=tid;t<65*64;t+=256){
        int k=t>>6, cc=t&63;
        ulonglong2 v = *(const ulonglong2*)&in[(size_t)k*CN + 2*cc];
        float cr,ci,dr,di; upk2(v.x,cr,ci); upk2(v.y,dr,di);
        if(k==0 || k==64){ ci = 0.0f; di = 0.0f; }
        xs[k*64+cc] = pk2(sc*(cr-di), sc*(ci+dr));
        if(k>=1 && k<=63)
            xs[(128-k)*64+cc] = pk2(sc*(cr+di), sc*(dr-ci));
    }
    if(tid<64) tws[tid] = *(const ulonglong2*)&g_twI[2*tid];
    __syncthreads();
    fft128(xs, tws, c, tg);   // inverse (e^{+i}), unnormalized

    size_t obase = (size_t)bh*(WN*CN) + cb;
    for(int s=tid;s<8192;s+=256){
        int islot=s>>6, cc=s&63;
        int w = __brev(islot)>>25;
        float yr,yi; upk2(xs[s], yr, yi);
        size_t off = obase + (size_t)w*CN + 2*cc;
        float2 bv = *(const float2*)&x[off];
        *(float2*)&y[off] = make_float2(yr+bv.x, yi+bv.y);
    }
}

// ---------------------------------------------------------------------------
extern "C" void kernel_launch(void* const* d_in, const int* in_sizes, int n_in,
                              void* d_out, int out_size) {
    const float* x  = (const float*)d_in[0];
    const float* w1 = (const float*)d_in[1];
    const float* w2 = (const float*)d_in[2];
    const float* b1 = (const float*)d_in[3];
    const float* b2 = (const float*)d_in[4];
    float* y = (float*)d_out;

    cudaFuncSetAttribute(k_s1,   cudaFuncAttributeMaxDynamicSharedMemorySize, FFT_SMEM);
    cudaFuncSetAttribute(k_ffth, cudaFuncAttributeMaxDynamicSharedMemorySize, FFT_SMEM);
    cudaFuncSetAttribute(k_s5,   cudaFuncAttributeMaxDynamicSharedMemorySize, FFT_SMEM);
    cudaFuncSetAttribute(k_mlp,  cudaFuncAttributeMaxDynamicSharedMemorySize, MLP_SMEM);

    k_init<<<1,128>>>();
    k_s1  <<<dim3(512,6), 256, FFT_SMEM>>>(x);
    k_ffth<<<dim3(260,12),256, FFT_SMEM>>>(0);
    k_mlp <<<dim3(130,16),256, MLP_SMEM>>>(0, w1, b1);
    k_mlp <<<dim3(130,16),256, MLP_SMEM>>>(1, w2, b2);
    k_ffth<<<dim3(260,12),256, FFT_SMEM>>>(1);
    k_s5  <<<dim3(512,6), 256, FFT_SMEM>>>(x, y);
    (void)in_sizes; (void)n_in; (void)out_size;
}

// round 6
// speedup vs baseline: 2.3609x; 1.0108x over previous
#include <cuda_runtime.h>
#include <math.h>

typedef unsigned long long u64;

#define BN 4
#define HN 128
#define WN 128
#define CN 768
#define WFQ 65
#define ROWST (WFQ*CN)              /* 49920 u64 per (b,h) row */
#define NELEM (BN*HN*WFQ*CN)        /* 25,559,040 complex */

// Scratch complex buffers (re = low 32 bits, im = high 32 bits)
__device__ __align__(128) u64 g_A[NELEM];
__device__ __align__(128) u64 g_B[NELEM];
// Twiddle tables (128th roots of unity), cmul-ready pairs
__device__ __align__(16) u64 g_twF[256];   // pairs (c,c),(s,-s)   fwd  e^{-i}
__device__ __align__(16) u64 g_twI[256];   // pairs (c,c),(-s,s)   inv  e^{+i}

__device__ __forceinline__ u64 pk2(float lo, float hi){
    u64 r; asm("mov.b64 %0,{%1,%2};":"=l"(r):"f"(lo),"f"(hi)); return r;
}
__device__ __forceinline__ void upk2(u64 v, float& lo, float& hi){
    asm("mov.b64 {%0,%1},%2;":"=f"(lo),"=f"(hi):"l"(v));
}
__device__ __forceinline__ u64 fma2(u64 a, u64 b, u64 c){
    u64 d; asm("fma.rn.f32x2 %0,%1,%2,%3;":"=l"(d):"l"(a),"l"(b),"l"(c)); return d;
}
__device__ __forceinline__ u64 mul2(u64 a, u64 b){
    u64 d; asm("mul.rn.f32x2 %0,%1,%2;":"=l"(d):"l"(a),"l"(b)); return d;
}
__device__ __forceinline__ u64 add2(u64 a, u64 b){
    u64 d; asm("add.rn.f32x2 %0,%1,%2;":"=l"(d):"l"(a),"l"(b)); return d;
}
__device__ __forceinline__ u64 swp2(u64 v){
    float lo,hi; upk2(v,lo,hi); return pk2(hi,lo);
}
__device__ __forceinline__ float sshrink(float v){
    return copysignf(fmaxf(fabsf(v)-0.01f,0.0f), v);
}

// ---------------------------------------------------------------------------
__global__ void k_init(){
    int j = threadIdx.x;                 // 128 threads
    double a = (double)j * (3.14159265358979323846/64.0);
    float c = (float)cos(a), s = (float)sin(a);
    g_twF[2*j]   = pk2(c,c);  g_twF[2*j+1] = pk2(s,-s);
    g_twI[2*j]   = pk2(c,c);  g_twI[2*j+1] = pk2(-s,s);
}

// ---------------------------------------------------------------------------
// In-smem 128-point radix-2 DIF FFT over xs[128 pts][64 cols] (u64 packed
// complex). 256 threads: c = tid&63, tg = tid>>6 (4 groups x 16 butterflies).
// On exit, slot i holds X[bitrev7(i)]. Caller syncs are inside.
__device__ __forceinline__ void fft128(u64* xs, const ulonglong2* tws,
                                       int c, int tg){
    const u64 NEG1 = 0xBF800000BF800000ULL; // (-1.f,-1.f)
    #pragma unroll 1
    for(int lm=6; lm>=0; lm--){
        int m = 1<<lm;
        #pragma unroll
        for(int u=0; u<16; u++){
            int t = tg*16+u;
            int j = t & (m-1);
            int i1 = ((t>>lm)<<(lm+1)) + j;
            int i2 = i1 + m;
            u64 a = xs[i1*64+c], b = xs[i2*64+c];
            u64 sum = add2(a,b);
            u64 dif = fma2(b, NEG1, a);
            ulonglong2 w = tws[j<<(6-lm)];
            u64 res = fma2(swp2(dif), w.y, mul2(dif, w.x));
            xs[i1*64+c] = sum;
            xs[i2*64+c] = res;
        }
        __syncthreads();
    }
}

#define FFT_SMEM (65536 + 1024)

// ---------------------------------------------------------------------------
// Stage 1: rfft along W, two real channels packed per complex FFT.
// grid (B*H=512, 6 tiles of 128 channels), 256 thr.
// out: g_A[b,h,k,c] = X[k] scaled by 1/128 (full fwd ortho factor), k<65.
__global__ void __launch_bounds__(256) k_s1(const float* __restrict__ x){
    extern __shared__ __align__(16) char smraw[];
    u64* xs = (u64*)smraw;                       // [128][64]
    ulonglong2* tws = (ulonglong2*)(smraw + 65536);
    int tid = threadIdx.x, c = tid&63, tg = tid>>6;
    int bh = blockIdx.x, cb = blockIdx.y*128;
    const float* xin = x + (size_t)bh*(WN*CN) + cb;
    for(int i=tid;i<8192;i+=256){
        int w=i>>6, cc=i&63;
        float2 v = *(const float2*)&xin[(size_t)w*CN + 2*cc];
        xs[i] = pk2(v.x, v.y);
    }
    if(tid<64) tws[tid] = *(const ulonglong2*)&g_twF[2*tid];
    __syncthreads();
    fft128(xs, tws, c, tg);

    // unscramble: Xc = (Z[k]+conj(Z[-k]))/2 ; Xd = -i(Z[k]-conj(Z[-k]))/2
    u64* ob = g_A + (size_t)bh*ROWST + cb;
    const float sc = 1.0f/256.0f;   // 0.5 * (1/128 ortho)
    for(int k=tg; k<65; k+=4){
        int s1 = __brev(k)>>25;
        int s2 = __brev((128-k)&127)>>25;
        u64 Z = xs[s1*64+c], Zm = xs[s2*64+c];
        float a,b,p,q; upk2(Z,a,b); upk2(Zm,p,q);
        ulonglong2 st;
        st.x = pk2(sc*(a+p), sc*(b-q));
        st.y = pk2(sc*(b+q), sc*(p-a));
        *(ulonglong2*)&ob[(size_t)k*CN + 2*c] = st;
    }
}

// ---------------------------------------------------------------------------
// Stage 2/4: complex FFT along H. dir=0: fwd g_A->g_B. dir=1: inv g_B->g_A.
// grid (B*65=260, 12 tiles of 64 channels), 256 thr.
__global__ void __launch_bounds__(256) k_ffth(int dir){
    extern __shared__ __align__(16) char smraw[];
    u64* xs = (u64*)smraw;
    ulonglong2* tws = (ulonglong2*)(smraw + 65536);
    int tid = threadIdx.x, c = tid&63, tg = tid>>6;
    int b = blockIdx.x / WFQ, wf = blockIdx.x % WFQ;
    int cb = blockIdx.y*64;
    const u64* in = dir ? g_B : g_A;
    u64* out      = dir ? g_A : g_B;
    size_t base = (size_t)b*HN*ROWST + (size_t)wf*CN + cb;

    for(int i=tid;i<4096;i+=256){
        int h=i>>5, cp=i&31;
        ulonglong2 v = *(const ulonglong2*)(in + base + (size_t)h*ROWST + 2*cp);
        *(ulonglong2*)&xs[h*64 + 2*cp] = v;
    }
    if(tid<64) tws[tid] = *(const ulonglong2*)(dir ? &g_twI[2*tid] : &g_twF[2*tid]);
    __syncthreads();
    fft128(xs, tws, c, tg);

    for(int s=tid;s<4096;s+=256){
        int islot=s>>5, cp=s&31;
        int k = __brev(islot)>>25;
        ulonglong2 v = *(const ulonglong2*)&xs[islot*64 + 2*cp];
        *(ulonglong2*)(out + base + (size_t)k*ROWST + 2*cp) = v;
    }
}

// ---------------------------------------------------------------------------
// Stage 3: one complex block-diagonal MLP layer with softshrink.
// Register-blocked: 2 points x 12 outputs per thread (fits 2 CTA/SM).
// x streamed directly from global; weights broadcast from smem SoA planes.
// grid (260 point-tiles of 128, 16 = 8 kb x 2 output-halves of 48). 256 thr
// = 64 point-lanes x 4 output-subgroups of 12.
#define MLP_WR    0
#define MLP_WI    18432
#define MLP_BS    36864
#define MLP_SMEM  37376
__global__ void __launch_bounds__(256,2) k_mlp(int which, const float* __restrict__ w,
                                               const float* __restrict__ bvec){
    extern __shared__ __align__(16) char smraw[];
    float*  wr_s = (float*)(smraw + MLP_WR);
    float*  wi_s = (float*)(smraw + MLP_WI);
    float2* bs   = (float2*)(smraw + MLP_BS);
    int tid = threadIdx.x;
    int P0 = blockIdx.x*128;
    int kb = blockIdx.y & 7, o0 = (blockIdx.y>>3)*48;
    const u64* in = which ? g_A : g_B;
    u64* out      = which ? g_B : g_A;

    for(int t=tid;t<4608;t+=256){
        int i = t/48, oo = t - i*48;
        wr_s[t] = w[(size_t)kb*9216 + i*96 + o0 + oo];
        wi_s[t] = w[(size_t)(8+kb)*9216 + i*96 + o0 + oo];
    }
    if(tid<48) bs[tid] = make_float2(bvec[kb*96 + o0 + tid],
                                     bvec[768 + kb*96 + o0 + tid]);
    __syncthreads();

    int pl = tid&63, og = tid>>6, ob = og*12;
    const u64* xb0 = in + (size_t)(P0 + pl*2)*CN + kb*96;

    u64 are[2][6], aim[2][6];
    #pragma unroll
    for(int k=0;k<6;k++){
        float2 b0 = bs[ob+2*k], b1 = bs[ob+2*k+1];
        u64 r = pk2(b0.x,b1.x), m = pk2(b0.y,b1.y);
        are[0][k]=r; aim[0][k]=m;
        are[1][k]=r; aim[1][k]=m;
    }

    #pragma unroll 1
    for(int i=0;i<96;i+=4){
        ulonglong2 xa[2], xb[2];
        #pragma unroll
        for(int t=0;t<2;t++){
            const u64* p = xb0 + (size_t)t*CN + i;
            xa[t] = *(const ulonglong2*)p;
            xb[t] = *(const ulonglong2*)(p+2);
        }
        #pragma unroll
        for(int ii=0;ii<4;ii++){
            const ulonglong2* wrp = (const ulonglong2*)&wr_s[(i+ii)*48 + ob];
            const ulonglong2* wip = (const ulonglong2*)&wi_s[(i+ii)*48 + ob];
            ulonglong2 wa = wrp[0], wb = wrp[1], wc = wrp[2];
            ulonglong2 va = wip[0], vb = wip[1], vc = wip[2];
            u64 wreg[6]; u64 vreg[6];
            wreg[0]=wa.x; wreg[1]=wa.y; wreg[2]=wb.x; wreg[3]=wb.y; wreg[4]=wc.x; wreg[5]=wc.y;
            vreg[0]=va.x; vreg[1]=va.y; vreg[2]=vb.x; vreg[3]=vb.y; vreg[4]=vc.x; vreg[5]=vc.y;
            #pragma unroll
            for(int t=0;t<2;t++){
                u64 xv = (ii==0) ? xa[t].x : (ii==1) ? xa[t].y
                       : (ii==2) ? xb[t].x : xb[t].y;
                float xr,xi; upk2(xv,xr,xi);
                u64 rr=pk2(xr,xr), iv=pk2(xi,xi), nii=pk2(-xi,-xi);
                #pragma unroll
                for(int k=0;k<6;k++){
                    are[t][k]=fma2(rr, wreg[k],are[t][k]);
                    are[t][k]=fma2(nii,vreg[k],are[t][k]);
                    aim[t][k]=fma2(iv, wreg[k],aim[t][k]);
                    aim[t][k]=fma2(rr, vreg[k],aim[t][k]);
                }
            }
        }
    }

    u64* obp = out + (size_t)(P0 + pl*2)*CN + kb*96 + o0 + ob;
    #pragma unroll
    for(int t=0;t<2;t++){
        u64* op = obp + (size_t)t*CN;
        #pragma unroll
        for(int k=0;k<3;k++){
            float r0,r1,i0,i1,r2,r3,i2,i3;
            upk2(are[t][2*k],  r0,r1); upk2(aim[t][2*k],  i0,i1);
            upk2(are[t][2*k+1],r2,r3); upk2(aim[t][2*k+1],i2,i3);
            ulonglong2 s0, s1;
            s0.x = pk2(sshrink(r0), sshrink(i0));
            s0.y = pk2(sshrink(r1), sshrink(i1));
            s1.x = pk2(sshrink(r2), sshrink(i2));
            s1.y = pk2(sshrink(r3), sshrink(i3));
            *(ulonglong2*)(op + 4*k)     = s0;
            *(ulonglong2*)(op + 4*k + 2) = s1;
        }
    }
}

// ---------------------------------------------------------------------------
// Stage 5: irfft along W + residual, two real outputs packed per complex FFT.
// grid (512, 6 tiles of 128 channels), 256 thr.
__global__ void __launch_bounds__(256) k_s5(const float* __restrict__ x,
                                            float* __restrict__ y){
    extern __shared__ __align__(16) char smraw[];
    u64* xs = (u64*)smraw;
    ulonglong2* tws = (ulonglong2*)(smraw + 65536);
    int tid = threadIdx.x, c = tid&63, tg = tid>>6;
    int bh = blockIdx.x, cb = blockIdx.y*128;
    const u64* in = g_A + (size_t)bh*ROWST + cb;
    const float sc = 1.0f/128.0f;   // inverse ortho total

    // Build paired spectrum Z[k] = Xc[k] + i*Xd[k], hermitian-extended.
    // pocketfft C2R ignores Im at DC/Nyquist -> zero them.
    for(int t=tid;t<65*64;t+=256){
        int k=t>>6, cc=t&63;
        ulonglong2 v = *(const ulonglong2*)&in[(size_t)k*CN + 2*cc];
        float cr,ci,dr,di; upk2(v.x,cr,ci); upk2(v.y,dr,di);
        if(k==0 || k==64){ ci = 0.0f; di = 0.0f; }
        xs[k*64+cc] = pk2(sc*(cr-di), sc*(ci+dr));
        if(k>=1 && k<=63)
            xs[(128-k)*64+cc] = pk2(sc*(cr+di), sc*(dr-ci));
    }
    if(tid<64) tws[tid] = *(const ulonglong2*)&g_twI[2*tid];
    __syncthreads();
    fft128(xs, tws, c, tg);   // inverse (e^{+i}), unnormalized

    size_t obase = (size_t)bh*(WN*CN) + cb;
    for(int s=tid;s<8192;s+=256){
        int islot=s>>6, cc=s&63;
        int w = __brev(islot)>>25;
        float yr,yi; upk2(xs[s], yr, yi);
        size_t off = obase + (size_t)w*CN + 2*cc;
        float2 bv = *(const float2*)&x[off];
        *(float2*)&y[off] = make_float2(yr+bv.x, yi+bv.y);
    }
}

// ---------------------------------------------------------------------------
extern "C" void kernel_launch(void* const* d_in, const int* in_sizes, int n_in,
                              void* d_out, int out_size) {
    const float* x  = (const float*)d_in[0];
    const float* w1 = (const float*)d_in[1];
    const float* w2 = (const float*)d_in[2];
    const float* b1 = (const float*)d_in[3];
    const float* b2 = (const float*)d_in[4];
    float* y = (float*)d_out;

    cudaFuncSetAttribute(k_s1,   cudaFuncAttributeMaxDynamicSharedMemorySize, FFT_SMEM);
    cudaFuncSetAttribute(k_ffth, cudaFuncAttributeMaxDynamicSharedMemorySize, FFT_SMEM);
    cudaFuncSetAttribute(k_s5,   cudaFuncAttributeMaxDynamicSharedMemorySize, FFT_SMEM);
    cudaFuncSetAttribute(k_mlp,  cudaFuncAttributeMaxDynamicSharedMemorySize, MLP_SMEM);

    k_init<<<1,128>>>();
    k_s1  <<<dim3(512,6), 256, FFT_SMEM>>>(x);
    k_ffth<<<dim3(260,12),256, FFT_SMEM>>>(0);
    k_mlp <<<dim3(260,16),256, MLP_SMEM>>>(0, w1, b1);
    k_mlp <<<dim3(260,16),256, MLP_SMEM>>>(1, w2, b2);
    k_ffth<<<dim3(260,12),256, FFT_SMEM>>>(1);
    k_s5  <<<dim3(512,6), 256, FFT_SMEM>>>(x, y);
    (void)in_sizes; (void)n_in; (void)out_size;
}

// round 7
// speedup vs baseline: 2.4144x; 1.0227x over previous
#include <cuda_runtime.h>
#include <math.h>

typedef unsigned long long u64;

#define BN 4
#define HN 128
#define WN 128
#define CN 768
#define WFQ 65
#define ROWST (WFQ*CN)              /* 49920 u64 per (b,h) row */
#define NELEM (BN*HN*WFQ*CN)        /* 25,559,040 complex */

// Scratch complex buffers (re = low 32 bits, im = high 32 bits)
__device__ __align__(128) u64 g_A[NELEM];
__device__ __align__(128) u64 g_B[NELEM];
// Twiddle tables (128th roots of unity), cmul-ready pairs
__device__ __align__(16) u64 g_twF[256];   // pairs (c,c),(s,-s)   fwd  e^{-i}
__device__ __align__(16) u64 g_twI[256];   // pairs (c,c),(-s,s)   inv  e^{+i}

__device__ __forceinline__ u64 pk2(float lo, float hi){
    u64 r; asm("mov.b64 %0,{%1,%2};":"=l"(r):"f"(lo),"f"(hi)); return r;
}
__device__ __forceinline__ void upk2(u64 v, float& lo, float& hi){
    asm("mov.b64 {%0,%1},%2;":"=f"(lo),"=f"(hi):"l"(v));
}
__device__ __forceinline__ u64 fma2(u64 a, u64 b, u64 c){
    u64 d; asm("fma.rn.f32x2 %0,%1,%2,%3;":"=l"(d):"l"(a),"l"(b),"l"(c)); return d;
}
__device__ __forceinline__ u64 mul2(u64 a, u64 b){
    u64 d; asm("mul.rn.f32x2 %0,%1,%2;":"=l"(d):"l"(a),"l"(b)); return d;
}
__device__ __forceinline__ u64 add2(u64 a, u64 b){
    u64 d; asm("add.rn.f32x2 %0,%1,%2;":"=l"(d):"l"(a),"l"(b)); return d;
}
__device__ __forceinline__ u64 swp2(u64 v){
    float lo,hi; upk2(v,lo,hi); return pk2(hi,lo);
}
__device__ __forceinline__ float sshrink(float v){
    return copysignf(fmaxf(fabsf(v)-0.01f,0.0f), v);
}

// ---------------------------------------------------------------------------
__global__ void k_init(){
    int j = threadIdx.x;                 // 128 threads
    double a = (double)j * (3.14159265358979323846/64.0);
    float c = (float)cos(a), s = (float)sin(a);
    g_twF[2*j]   = pk2(c,c);  g_twF[2*j+1] = pk2(s,-s);
    g_twI[2*j]   = pk2(c,c);  g_twI[2*j+1] = pk2(-s,s);
}

// ---------------------------------------------------------------------------
// In-smem 128-point radix-2 DIF FFT over xs[128 pts][64 cols] (u64 packed
// complex). 256 threads: c = tid&63, tg = tid>>6 (4 groups x 16 butterflies).
// On exit, slot i holds X[bitrev7(i)]. Caller syncs are inside.
__device__ __forceinline__ void fft128(u64* xs, const ulonglong2* tws,
                                       int c, int tg){
    const u64 NEG1 = 0xBF800000BF800000ULL; // (-1.f,-1.f)
    #pragma unroll 1
    for(int lm=6; lm>=0; lm--){
        int m = 1<<lm;
        #pragma unroll
        for(int u=0; u<16; u++){
            int t = tg*16+u;
            int j = t & (m-1);
            int i1 = ((t>>lm)<<(lm+1)) + j;
            int i2 = i1 + m;
            u64 a = xs[i1*64+c], b = xs[i2*64+c];
            u64 sum = add2(a,b);
            u64 dif = fma2(b, NEG1, a);
            ulonglong2 w = tws[j<<(6-lm)];
            u64 res = fma2(swp2(dif), w.y, mul2(dif, w.x));
            xs[i1*64+c] = sum;
            xs[i2*64+c] = res;
        }
        __syncthreads();
    }
}

#define FFT_SMEM (65536 + 1024)

// ---------------------------------------------------------------------------
// Stage 1: rfft along W, two real channels packed per complex FFT.
// grid (B*H=512, 6 tiles of 128 channels), 256 thr.
// out: g_A[b,h,k,c] = X[k] scaled by 1/128 (full fwd ortho factor), k<65.
__global__ void __launch_bounds__(256) k_s1(const float* __restrict__ x){
    extern __shared__ __align__(16) char smraw[];
    u64* xs = (u64*)smraw;                       // [128][64]
    ulonglong2* tws = (ulonglong2*)(smraw + 65536);
    int tid = threadIdx.x, c = tid&63, tg = tid>>6;
    int bh = blockIdx.x, cb = blockIdx.y*128;
    const float* xin = x + (size_t)bh*(WN*CN) + cb;
    for(int i=tid;i<8192;i+=256){
        int w=i>>6, cc=i&63;
        float2 v = *(const float2*)&xin[(size_t)w*CN + 2*cc];
        xs[i] = pk2(v.x, v.y);
    }
    if(tid<64) tws[tid] = *(const ulonglong2*)&g_twF[2*tid];
    __syncthreads();
    fft128(xs, tws, c, tg);

    // unscramble: Xc = (Z[k]+conj(Z[-k]))/2 ; Xd = -i(Z[k]-conj(Z[-k]))/2
    u64* ob = g_A + (size_t)bh*ROWST + cb;
    const float sc = 1.0f/256.0f;   // 0.5 * (1/128 ortho)
    for(int k=tg; k<65; k+=4){
        int s1 = __brev(k)>>25;
        int s2 = __brev((128-k)&127)>>25;
        u64 Z = xs[s1*64+c], Zm = xs[s2*64+c];
        float a,b,p,q; upk2(Z,a,b); upk2(Zm,p,q);
        ulonglong2 st;
        st.x = pk2(sc*(a+p), sc*(b-q));
        st.y = pk2(sc*(b+q), sc*(p-a));
        *(ulonglong2*)&ob[(size_t)k*CN + 2*c] = st;
    }
}

// ---------------------------------------------------------------------------
// Stage 2/4: complex FFT along H. dir=0: fwd g_A->g_B. dir=1: inv g_B->g_A.
// grid (B*65=260, 12 tiles of 64 channels), 256 thr.
__global__ void __launch_bounds__(256) k_ffth(int dir){
    extern __shared__ __align__(16) char smraw[];
    u64* xs = (u64*)smraw;
    ulonglong2* tws = (ulonglong2*)(smraw + 65536);
    int tid = threadIdx.x, c = tid&63, tg = tid>>6;
    int b = blockIdx.x / WFQ, wf = blockIdx.x % WFQ;
    int cb = blockIdx.y*64;
    const u64* in = dir ? g_B : g_A;
    u64* out      = dir ? g_A : g_B;
    size_t base = (size_t)b*HN*ROWST + (size_t)wf*CN + cb;

    for(int i=tid;i<4096;i+=256){
        int h=i>>5, cp=i&31;
        ulonglong2 v = *(const ulonglong2*)(in + base + (size_t)h*ROWST + 2*cp);
        *(ulonglong2*)&xs[h*64 + 2*cp] = v;
    }
    if(tid<64) tws[tid] = *(const ulonglong2*)(dir ? &g_twI[2*tid] : &g_twF[2*tid]);
    __syncthreads();
    fft128(xs, tws, c, tg);

    for(int s=tid;s<4096;s+=256){
        int islot=s>>5, cp=s&31;
        int k = __brev(islot)>>25;
        ulonglong2 v = *(const ulonglong2*)&xs[islot*64 + 2*cp];
        *(ulonglong2*)(out + base + (size_t)k*ROWST + 2*cp) = v;
    }
}

// ---------------------------------------------------------------------------
// Stage 3: one complex block-diagonal MLP layer with softshrink.
// Hybrid: x staged through smem in transposed [i][p] layout (coalesced LDG
// in, conflict-free LDS.128 out), staged in two 48-i chunks to keep smem at
// 87KB -> 2 CTAs/SM. Thread = 2 points x 6 output-pairs -> 48 fma2 per
// i-step against ~7 LDS, fma-pipe bound.
// grid (260 point-tiles of 128, 16 = 8 kb x 2 output-halves of 48). 256 thr
// = 64 point-lanes x 4 output-subgroups of 12.
#define MLP_XS    0
#define MLP_WR    49920
#define MLP_WI    68352
#define MLP_BS    86784
#define MLP_SMEM  87168
__global__ void __launch_bounds__(256,2) k_mlp(int which, const float* __restrict__ w,
                                               const float* __restrict__ bvec){
    extern __shared__ __align__(16) char smraw[];
    u64*    xs   = (u64*)(smraw + MLP_XS);       // [48 i][130 p]
    float*  wr_s = (float*)(smraw + MLP_WR);     // [96 i][48 o]
    float*  wi_s = (float*)(smraw + MLP_WI);
    float2* bs   = (float2*)(smraw + MLP_BS);
    int tid = threadIdx.x;
    int P0 = blockIdx.x*128;
    int kb = blockIdx.y & 7, o0 = (blockIdx.y>>3)*48;
    const u64* in = which ? g_A : g_B;
    u64* out      = which ? g_B : g_A;

    for(int t=tid;t<4608;t+=256){
        int i = t/48, oo = t - i*48;
        wr_s[t] = w[(size_t)kb*9216 + i*96 + o0 + oo];
        wi_s[t] = w[(size_t)(8+kb)*9216 + i*96 + o0 + oo];
    }
    if(tid<48) bs[tid] = make_float2(bvec[kb*96 + o0 + tid],
                                     bvec[768 + kb*96 + o0 + tid]);
    __syncthreads();

    int pl = tid&63, og = tid>>6, ob = og*12;
    u64 are[2][6], aim[2][6];
    #pragma unroll
    for(int k=0;k<6;k++){
        float2 b0 = bs[ob+2*k], b1 = bs[ob+2*k+1];
        u64 r = pk2(b0.x,b1.x), m = pk2(b0.y,b1.y);
        are[0][k]=r; aim[0][k]=m;
        are[1][k]=r; aim[1][k]=m;
    }

    #pragma unroll 1
    for(int ch=0; ch<2; ch++){
        if(ch) __syncthreads();   // prior chunk's reads done before overwrite
        // stage x chunk: [i 0..47][p 0..127], coalesced global reads
        for(int n=tid;n<6144;n+=256){
            int p = n/48, i = n - p*48;
            xs[i*130 + p] = in[(size_t)(P0+p)*CN + kb*96 + ch*48 + i];
        }
        __syncthreads();
        const float* wrb = wr_s + (ch*48)*48 + ob;
        const float* wib = wi_s + (ch*48)*48 + ob;
        #pragma unroll 2
        for(int i=0;i<48;i++){
            ulonglong2 xv = *(const ulonglong2*)&xs[i*130 + 2*pl];
            const ulonglong2* wrp = (const ulonglong2*)(wrb + i*48);
            const ulonglong2* wip = (const ulonglong2*)(wib + i*48);
            ulonglong2 wa = wrp[0], wb = wrp[1], wc = wrp[2];
            ulonglong2 va = wip[0], vb = wip[1], vc = wip[2];
            u64 wreg[6]; u64 vreg[6];
            wreg[0]=wa.x; wreg[1]=wa.y; wreg[2]=wb.x; wreg[3]=wb.y; wreg[4]=wc.x; wreg[5]=wc.y;
            vreg[0]=va.x; vreg[1]=va.y; vreg[2]=vb.x; vreg[3]=vb.y; vreg[4]=vc.x; vreg[5]=vc.y;
            #pragma unroll
            for(int t=0;t<2;t++){
                u64 xvt = t ? xv.y : xv.x;
                float xr,xi; upk2(xvt,xr,xi);
                u64 rr=pk2(xr,xr), iv=pk2(xi,xi), nii=pk2(-xi,-xi);
                #pragma unroll
                for(int k=0;k<6;k++){
                    are[t][k]=fma2(rr, wreg[k],are[t][k]);
                    are[t][k]=fma2(nii,vreg[k],are[t][k]);
                    aim[t][k]=fma2(iv, wreg[k],aim[t][k]);
                    aim[t][k]=fma2(rr, vreg[k],aim[t][k]);
                }
            }
        }
    }

    u64* obp = out + (size_t)(P0 + 2*pl)*CN + kb*96 + o0 + ob;
    #pragma unroll
    for(int t=0;t<2;t++){
        u64* op = obp + (size_t)t*CN;
        #pragma unroll
        for(int k=0;k<3;k++){
            float r0,r1,i0,i1,r2,r3,i2,i3;
            upk2(are[t][2*k],  r0,r1); upk2(aim[t][2*k],  i0,i1);
            upk2(are[t][2*k+1],r2,r3); upk2(aim[t][2*k+1],i2,i3);
            ulonglong2 s0, s1;
            s0.x = pk2(sshrink(r0), sshrink(i0));
            s0.y = pk2(sshrink(r1), sshrink(i1));
            s1.x = pk2(sshrink(r2), sshrink(i2));
            s1.y = pk2(sshrink(r3), sshrink(i3));
            *(ulonglong2*)(op + 4*k)     = s0;
            *(ulonglong2*)(op + 4*k + 2) = s1;
        }
    }
}

// ---------------------------------------------------------------------------
// Stage 5: irfft along W + residual, two real outputs packed per complex FFT.
// grid (512, 6 tiles of 128 channels), 256 thr.
__global__ void __launch_bounds__(256) k_s5(const float* __restrict__ x,
                                            float* __restrict__ y){
    extern __shared__ __align__(16) char smraw[];
    u64* xs = (u64*)smraw;
    ulonglong2* tws = (ulonglong2*)(smraw + 65536);
    int tid = threadIdx.x, c = tid&63, tg = tid>>6;
    int bh = blockIdx.x, cb = blockIdx.y*128;
    const u64* in = g_A + (size_t)bh*ROWST + cb;
    const float sc = 1.0f/128.0f;   // inverse ortho total

    // Build paired spectrum Z[k] = Xc[k] + i*Xd[k], hermitian-extended.
    // pocketfft C2R ignores Im at DC/Nyquist -> zero them.
    for(int t=tid;t<65*64;t+=256){
        int k=t>>6, cc=t&63;
        ulonglong2 v = *(const ulonglong2*)&in[(size_t)k*CN + 2*cc];
        float cr,ci,dr,di; upk2(v.x,cr,ci); upk2(v.y,dr,di);
        if(k==0 || k==64){ ci = 0.0f; di = 0.0f; }
        xs[k*64+cc] = pk2(sc*(cr-di), sc*(ci+dr));
        if(k>=1 && k<=63)
            xs[(128-k)*64+cc] = pk2(sc*(cr+di), sc*(dr-ci));
    }
    if(tid<64) tws[tid] = *(const ulonglong2*)&g_twI[2*tid];
    __syncthreads();
    fft128(xs, tws, c, tg);   // inverse (e^{+i}), unnormalized

    size_t obase = (size_t)bh*(WN*CN) + cb;
    for(int s=tid;s<8192;s+=256){
        int islot=s>>6, cc=s&63;
        int w = __brev(islot)>>25;
        float yr,yi; upk2(xs[s], yr, yi);
        size_t off = obase + (size_t)w*CN + 2*cc;
        float2 bv = *(const float2*)&x[off];
        *(float2*)&y[off] = make_float2(yr+bv.x, yi+bv.y);
    }
}

// ---------------------------------------------------------------------------
extern "C" void kernel_launch(void* const* d_in, const int* in_sizes, int n_in,
                              void* d_out, int out_size) {
    const float* x  = (const float*)d_in[0];
    const float* w1 = (const float*)d_in[1];
    const float* w2 = (const float*)d_in[2];
    const float* b1 = (const float*)d_in[3];
    const float* b2 = (const float*)d_in[4];
    float* y = (float*)d_out;

    cudaFuncSetAttribute(k_s1,   cudaFuncAttributeMaxDynamicSharedMemorySize, FFT_SMEM);
    cudaFuncSetAttribute(k_ffth, cudaFuncAttributeMaxDynamicSharedMemorySize, FFT_SMEM);
    cudaFuncSetAttribute(k_s5,   cudaFuncAttributeMaxDynamicSharedMemorySize, FFT_SMEM);
    cudaFuncSetAttribute(k_mlp,  cudaFuncAttributeMaxDynamicSharedMemorySize, MLP_SMEM);

    k_init<<<1,128>>>();
    k_s1  <<<dim3(512,6), 256, FFT_SMEM>>>(x);
    k_ffth<<<dim3(260,12),256, FFT_SMEM>>>(0);
    k_mlp <<<dim3(260,16),256, MLP_SMEM>>>(0, w1, b1);
    k_mlp <<<dim3(260,16),256, MLP_SMEM>>>(1, w2, b2);
    k_ffth<<<dim3(260,12),256, FFT_SMEM>>>(1);
    k_s5  <<<dim3(512,6), 256, FFT_SMEM>>>(x, y);
    (void)in_sizes; (void)n_in; (void)out_size;
}

// round 8
// speedup vs baseline: 2.5183x; 1.0430x over previous
#include <cuda_runtime.h>
#include <math.h>

typedef unsigned long long u64;

#define BN 4
#define HN 128
#define WN 128
#define CN 768
#define WFQ 65
#define ROWST (WFQ*CN)              /* 49920 u64 per (b,h) row */
#define NELEM (BN*HN*WFQ*CN)        /* 25,559,040 complex */

// Scratch complex buffers (re = low 32 bits, im = high 32 bits)
__device__ __align__(128) u64 g_A[NELEM];
__device__ __align__(128) u64 g_B[NELEM];
// Twiddle tables (128th roots of unity), cmul-ready pairs
__device__ __align__(16) u64 g_twF[256];   // pairs (c,c),(s,-s)   fwd  e^{-i}
__device__ __align__(16) u64 g_twI[256];   // pairs (c,c),(-s,s)   inv  e^{+i}

__device__ __forceinline__ u64 pk2(float lo, float hi){
    u64 r; asm("mov.b64 %0,{%1,%2};":"=l"(r):"f"(lo),"f"(hi)); return r;
}
__device__ __forceinline__ void upk2(u64 v, float& lo, float& hi){
    asm("mov.b64 {%0,%1},%2;":"=f"(lo),"=f"(hi):"l"(v));
}
__device__ __forceinline__ u64 fma2(u64 a, u64 b, u64 c){
    u64 d; asm("fma.rn.f32x2 %0,%1,%2,%3;":"=l"(d):"l"(a),"l"(b),"l"(c)); return d;
}
__device__ __forceinline__ u64 mul2(u64 a, u64 b){
    u64 d; asm("mul.rn.f32x2 %0,%1,%2;":"=l"(d):"l"(a),"l"(b)); return d;
}
__device__ __forceinline__ u64 add2(u64 a, u64 b){
    u64 d; asm("add.rn.f32x2 %0,%1,%2;":"=l"(d):"l"(a),"l"(b)); return d;
}
__device__ __forceinline__ u64 swp2(u64 v){
    float lo,hi; upk2(v,lo,hi); return pk2(hi,lo);
}
__device__ __forceinline__ float sshrink(float v){
    return copysignf(fmaxf(fabsf(v)-0.01f,0.0f), v);
}
__device__ __forceinline__ u64 sshrink2(u64 v){
    float a,b; upk2(v,a,b); return pk2(sshrink(a), sshrink(b));
}

#define NEG1C 0xBF800000BF800000ULL  /* (-1.f,-1.f) */

__device__ __forceinline__ u64 cmul2(u64 v, ulonglong2 w){
    return fma2(swp2(v), w.y, mul2(v, w.x));
}

// ---------------------------------------------------------------------------
__global__ void k_init(){
    int j = threadIdx.x;                 // 128 threads
    double a = (double)j * (3.14159265358979323846/64.0);
    float c = (float)cos(a), s = (float)sin(a);
    g_twF[2*j]   = pk2(c,c);  g_twF[2*j+1] = pk2(s,-s);
    g_twI[2*j]   = pk2(c,c);  g_twI[2*j+1] = pk2(-s,s);
}

// ---------------------------------------------------------------------------
// In-smem 128-point radix-2 DIF FFT with fused stage pairs (bit-identical to
// the sequential radix-2 version). xs[128 pts][64 cols] u64 packed complex.
// 256 threads: c = tid&63, tg = tid>>6. 3 fused passes (lm = 6,4,2 each
// covering stages lm and lm-1) + final trivial stage. On exit, slot i holds
// X[bitrev7(i)].
__device__ __forceinline__ void fft128(u64* xs, const ulonglong2* tws,
                                       int c, int tg){
    #pragma unroll 1
    for(int lm=6; lm>=2; lm-=2){
        int m = 1<<lm, hm = m>>1;
        #pragma unroll
        for(int u=0; u<8; u++){
            int q = tg*8+u;                 // 0..31 quads
            int j = q & (hm-1);
            int blk = q >> (lm-1);
            int i0 = blk*2*m + j;
            u64 a = xs[i0*64+c],       b = xs[(i0+hm)*64+c];
            u64 d = xs[(i0+m)*64+c],   e = xs[(i0+m+hm)*64+c];
            int eA = j<<(6-lm);
            ulonglong2 wA  = tws[eA];
            ulonglong2 wA2 = tws[eA+32];
            ulonglong2 wB  = tws[2*eA];
            u64 s0 = add2(a,d), d0 = fma2(d,NEG1C,a);
            u64 s1 = add2(b,e), d1 = fma2(e,NEG1C,b);
            u64 r0 = cmul2(d0, wA);
            u64 r1 = cmul2(d1, wA2);
            xs[i0*64+c]        = add2(s0,s1);
            xs[(i0+hm)*64+c]   = cmul2(fma2(s1,NEG1C,s0), wB);
            xs[(i0+m)*64+c]    = add2(r0,r1);
            xs[(i0+m+hm)*64+c] = cmul2(fma2(r1,NEG1C,r0), wB);
        }
        __syncthreads();
    }
    // final stage (m=1), twiddle = 1
    #pragma unroll
    for(int u=0; u<16; u++){
        int t = tg*16+u;
        int i1 = 2*t;
        u64 a = xs[i1*64+c], b = xs[(i1+1)*64+c];
        xs[i1*64+c]     = add2(a,b);
        xs[(i1+1)*64+c] = fma2(b,NEG1C,a);
    }
    __syncthreads();
}

#define FFT_SMEM (65536 + 1024)

// ---------------------------------------------------------------------------
// Stage 1: rfft along W, two real channels packed per complex FFT.
// grid (B*H=512, 6 tiles of 128 channels), 256 thr.
__global__ void __launch_bounds__(256) k_s1(const float* __restrict__ x){
    extern __shared__ __align__(16) char smraw[];
    u64* xs = (u64*)smraw;                       // [128][64]
    ulonglong2* tws = (ulonglong2*)(smraw + 65536);
    int tid = threadIdx.x, c = tid&63, tg = tid>>6;
    int bh = blockIdx.x, cb = blockIdx.y*128;
    const float* xin = x + (size_t)bh*(WN*CN) + cb;
    for(int i=tid;i<8192;i+=256){
        int w=i>>6, cc=i&63;
        float2 v = *(const float2*)&xin[(size_t)w*CN + 2*cc];
        xs[i] = pk2(v.x, v.y);
    }
    if(tid<64) tws[tid] = *(const ulonglong2*)&g_twF[2*tid];
    __syncthreads();
    fft128(xs, tws, c, tg);

    // unscramble: Xc = (Z[k]+conj(Z[-k]))/2 ; Xd = -i(Z[k]-conj(Z[-k]))/2
    u64* ob = g_A + (size_t)bh*ROWST + cb;
    const float sc = 1.0f/256.0f;   // 0.5 * (1/128 ortho)
    for(int k=tg; k<65; k+=4){
        int s1 = __brev(k)>>25;
        int s2 = __brev((128-k)&127)>>25;
        u64 Z = xs[s1*64+c], Zm = xs[s2*64+c];
        float a,b,p,q; upk2(Z,a,b); upk2(Zm,p,q);
        ulonglong2 st;
        st.x = pk2(sc*(a+p), sc*(b-q));
        st.y = pk2(sc*(b+q), sc*(p-a));
        *(ulonglong2*)&ob[(size_t)k*CN + 2*c] = st;
    }
}

// ---------------------------------------------------------------------------
// Stage 2/4: complex FFT along H. dir=0: fwd g_A->g_B. dir=1: inv g_B->g_A.
// grid (B*65=260, 12 tiles of 64 channels), 256 thr.
__global__ void __launch_bounds__(256) k_ffth(int dir){
    extern __shared__ __align__(16) char smraw[];
    u64* xs = (u64*)smraw;
    ulonglong2* tws = (ulonglong2*)(smraw + 65536);
    int tid = threadIdx.x, c = tid&63, tg = tid>>6;
    int b = blockIdx.x / WFQ, wf = blockIdx.x % WFQ;
    int cb = blockIdx.y*64;
    const u64* in = dir ? g_B : g_A;
    u64* out      = dir ? g_A : g_B;
    size_t base = (size_t)b*HN*ROWST + (size_t)wf*CN + cb;

    for(int i=tid;i<4096;i+=256){
        int h=i>>5, cp=i&31;
        ulonglong2 v = *(const ulonglong2*)(in + base + (size_t)h*ROWST + 2*cp);
        *(ulonglong2*)&xs[h*64 + 2*cp] = v;
    }
    if(tid<64) tws[tid] = *(const ulonglong2*)(dir ? &g_twI[2*tid] : &g_twF[2*tid]);
    __syncthreads();
    fft128(xs, tws, c, tg);

    for(int s=tid;s<4096;s+=256){
        int islot=s>>5, cp=s&31;
        int k = __brev(islot)>>25;
        ulonglong2 v = *(const ulonglong2*)&xs[islot*64 + 2*cp];
        *(ulonglong2*)(out + base + (size_t)k*ROWST + 2*cp) = v;
    }
}

// ---------------------------------------------------------------------------
// Stage 3: one complex block-diagonal MLP layer with softshrink.
// Pre-splatted weight planes in smem: (wr,wr) and (-wi,wi) u64 — the hot
// loop has zero splat/unpack ALU: acc(re,im) += x*(wr,wr) + swp2(x)*(-wi,wi).
// x staged through smem transposed [i][p] in three 32-i chunks.
// grid (260 point-tiles of 128, 16 = 8 kb x 2 output-halves of 48). 256 thr
// = 64 point-lanes x 4 output-subgroups of 12. 2 CTAs/SM.
#define MLP_WR2   0
#define MLP_WI2   36864
#define MLP_BS    73728
#define MLP_XS    74112
#define MLP_SMEM  107392
__global__ void __launch_bounds__(256,2) k_mlp(int which, const float* __restrict__ w,
                                               const float* __restrict__ bvec){
    extern __shared__ __align__(16) char smraw[];
    u64* wr2 = (u64*)(smraw + MLP_WR2);      // [96 i][48 o] (wr,wr)
    u64* wi2 = (u64*)(smraw + MLP_WI2);      // [96 i][48 o] (-wi,wi)
    u64* bs  = (u64*)(smraw + MLP_BS);       // [48] (br,bi)
    u64* xs  = (u64*)(smraw + MLP_XS);       // [32 i][130 p]
    int tid = threadIdx.x;
    int P0 = blockIdx.x*128;
    int kb = blockIdx.y & 7, o0 = (blockIdx.y>>3)*48;
    const u64* in = which ? g_A : g_B;
    u64* out      = which ? g_B : g_A;

    for(int t=tid;t<4608;t+=256){
        int i = t/48, oo = t - i*48;
        float wr = w[(size_t)kb*9216 + i*96 + o0 + oo];
        float wi = w[(size_t)(8+kb)*9216 + i*96 + o0 + oo];
        wr2[t] = pk2(wr, wr);
        wi2[t] = pk2(-wi, wi);
    }
    if(tid<48) bs[tid] = pk2(bvec[kb*96 + o0 + tid],
                             bvec[768 + kb*96 + o0 + tid]);
    __syncthreads();

    int pl = tid&63, og = tid>>6, ob = og*12;
    u64 a0[12], a1[12];
    #pragma unroll
    for(int k=0;k<12;k++){ u64 bb = bs[ob+k]; a0[k]=bb; a1[k]=bb; }

    #pragma unroll 1
    for(int ch=0; ch<3; ch++){
        if(ch) __syncthreads();   // prior chunk's reads done before overwrite
        for(int n=tid;n<4096;n+=256){
            int p = n>>5, i = n&31;
            xs[i*130 + p] = in[(size_t)(P0+p)*CN + kb*96 + ch*32 + i];
        }
        __syncthreads();
        const u64* wrb = wr2 + (ch*32)*48 + ob;
        const u64* wib = wi2 + (ch*32)*48 + ob;
        #pragma unroll 2
        for(int i=0;i<32;i++){
            ulonglong2 xv = *(const ulonglong2*)&xs[i*130 + 2*pl];
            u64 x0 = xv.x, x1 = xv.y;
            u64 sx0 = swp2(x0), sx1 = swp2(x1);
            const ulonglong2* wp = (const ulonglong2*)(wrb + i*48);
            const ulonglong2* vp = (const ulonglong2*)(wib + i*48);
            #pragma unroll
            for(int k=0;k<6;k++){
                ulonglong2 wv = wp[k];
                ulonglong2 vv = vp[k];
                a0[2*k]   = fma2(x0,  wv.x, a0[2*k]);
                a0[2*k]   = fma2(sx0, vv.x, a0[2*k]);
                a1[2*k]   = fma2(x1,  wv.x, a1[2*k]);
                a1[2*k]   = fma2(sx1, vv.x, a1[2*k]);
                a0[2*k+1] = fma2(x0,  wv.y, a0[2*k+1]);
                a0[2*k+1] = fma2(sx0, vv.y, a0[2*k+1]);
                a1[2*k+1] = fma2(x1,  wv.y, a1[2*k+1]);
                a1[2*k+1] = fma2(sx1, vv.y, a1[2*k+1]);
            }
        }
    }

    u64* op0 = out + (size_t)(P0 + 2*pl)*CN + kb*96 + o0 + ob;
    u64* op1 = op0 + CN;
    #pragma unroll
    for(int k=0;k<6;k++){
        ulonglong2 s0, s1;
        s0.x = sshrink2(a0[2*k]);   s0.y = sshrink2(a0[2*k+1]);
        s1.x = sshrink2(a1[2*k]);   s1.y = sshrink2(a1[2*k+1]);
        *(ulonglong2*)(op0 + 2*k) = s0;
        *(ulonglong2*)(op1 + 2*k) = s1;
    }
}

// ---------------------------------------------------------------------------
// Stage 5: irfft along W + residual, two real outputs packed per complex FFT.
// grid (512, 6 tiles of 128 channels), 256 thr.
__global__ void __launch_bounds__(256) k_s5(const float* __restrict__ x,
                                            float* __restrict__ y){
    extern __shared__ __align__(16) char smraw[];
    u64* xs = (u64*)smraw;
    ulonglong2* tws = (ulonglong2*)(smraw + 65536);
    int tid = threadIdx.x, c = tid&63, tg = tid>>6;
    int bh = blockIdx.x, cb = blockIdx.y*128;
    const u64* in = g_A + (size_t)bh*ROWST + cb;
    const float sc = 1.0f/128.0f;   // inverse ortho total

    // Build paired spectrum Z[k] = Xc[k] + i*Xd[k], hermitian-extended.
    // pocketfft C2R ignores Im at DC/Nyquist -> zero them.
    for(int t=tid;t<65*64;t+=256){
        int k=t>>6, cc=t&63;
        ulonglong2 v = *(const ulonglong2*)&in[(size_t)k*CN + 2*cc];
        float cr,ci,dr,di; upk2(v.x,cr,ci); upk2(v.y,dr,di);
        if(k==0 || k==64){ ci = 0.0f; di = 0.0f; }
        xs[k*64+cc] = pk2(sc*(cr-di), sc*(ci+dr));
        if(k>=1 && k<=63)
            xs[(128-k)*64+cc] = pk2(sc*(cr+di), sc*(dr-ci));
    }
    if(tid<64) tws[tid] = *(const ulonglong2*)&g_twI[2*tid];
    __syncthreads();
    fft128(xs, tws, c, tg);   // inverse (e^{+i}), unnormalized

    size_t obase = (size_t)bh*(WN*CN) + cb;
    for(int s=tid;s<8192;s+=256){
        int islot=s>>6, cc=s&63;
        int w = __brev(islot)>>25;
        float yr,yi; upk2(xs[s], yr, yi);
        size_t off = obase + (size_t)w*CN + 2*cc;
        float2 bv = *(const float2*)&x[off];
        *(float2*)&y[off] = make_float2(yr+bv.x, yi+bv.y);
    }
}

// ---------------------------------------------------------------------------
extern "C" void kernel_launch(void* const* d_in, const int* in_sizes, int n_in,
                              void* d_out, int out_size) {
    const float* x  = (const float*)d_in[0];
    const float* w1 = (const float*)d_in[1];
    const float* w2 = (const float*)d_in[2];
    const float* b1 = (const float*)d_in[3];
    const float* b2 = (const float*)d_in[4];
    float* y = (float*)d_out;

    cudaFuncSetAttribute(k_s1,   cudaFuncAttributeMaxDynamicSharedMemorySize, FFT_SMEM);
    cudaFuncSetAttribute(k_ffth, cudaFuncAttributeMaxDynamicSharedMemorySize, FFT_SMEM);
    cudaFuncSetAttribute(k_s5,   cudaFuncAttributeMaxDynamicSharedMemorySize, FFT_SMEM);
    cudaFuncSetAttribute(k_mlp,  cudaFuncAttributeMaxDynamicSharedMemorySize, MLP_SMEM);

    k_init<<<1,128>>>();
    k_s1  <<<dim3(512,6), 256, FFT_SMEM>>>(x);
    k_ffth<<<dim3(260,12),256, FFT_SMEM>>>(0);
    k_mlp <<<dim3(260,16),256, MLP_SMEM>>>(0, w1, b1);
    k_mlp <<<dim3(260,16),256, MLP_SMEM>>>(1, w2, b2);
    k_ffth<<<dim3(260,12),256, FFT_SMEM>>>(1);
    k_s5  <<<dim3(512,6), 256, FFT_SMEM>>>(x, y);
    (void)in_sizes; (void)n_in; (void)out_size;
}

// round 10
// speedup vs baseline: 2.7560x; 1.0944x over previous
#include <cuda_runtime.h>
#include <math.h>

typedef unsigned long long u64;

#define BN 4
#define HN 128
#define WN 128
#define CN 768
#define WFQ 65
#define ROWST (WFQ*CN)              /* 49920 u64 per (b,h) row */
#define NELEM (BN*HN*WFQ*CN)        /* 25,559,040 complex */

// Scratch complex buffers (re = low 32 bits, im = high 32 bits)
__device__ __align__(128) u64 g_A[NELEM];
__device__ __align__(128) u64 g_B[NELEM];
// Twiddle tables (128th roots of unity), cmul-ready pairs
__device__ __align__(16) u64 g_twF[256];   // pairs (c,c),(s,-s)   fwd  e^{-i}
__device__ __align__(16) u64 g_twI[256];   // pairs (c,c),(-s,s)   inv  e^{+i}

__device__ __forceinline__ u64 pk2(float lo, float hi){
    u64 r; asm("mov.b64 %0,{%1,%2};":"=l"(r):"f"(lo),"f"(hi)); return r;
}
__device__ __forceinline__ void upk2(u64 v, float& lo, float& hi){
    asm("mov.b64 {%0,%1},%2;":"=f"(lo),"=f"(hi):"l"(v));
}
__device__ __forceinline__ u64 fma2(u64 a, u64 b, u64 c){
    u64 d; asm("fma.rn.f32x2 %0,%1,%2,%3;":"=l"(d):"l"(a),"l"(b),"l"(c)); return d;
}
__device__ __forceinline__ u64 mul2(u64 a, u64 b){
    u64 d; asm("mul.rn.f32x2 %0,%1,%2;":"=l"(d):"l"(a),"l"(b)); return d;
}
__device__ __forceinline__ u64 add2(u64 a, u64 b){
    u64 d; asm("add.rn.f32x2 %0,%1,%2;":"=l"(d):"l"(a),"l"(b)); return d;
}
__device__ __forceinline__ u64 swp2(u64 v){
    float lo,hi; upk2(v,lo,hi); return pk2(hi,lo);
}
__device__ __forceinline__ float sshrink(float v){
    return copysignf(fmaxf(fabsf(v)-0.01f,0.0f), v);
}

#define NEG1C 0xBF800000BF800000ULL  /* (-1.f,-1.f) */

__device__ __forceinline__ u64 cmul2(u64 v, ulonglong2 w){
    return fma2(swp2(v), w.y, mul2(v, w.x));
}

// ---------------------------------------------------------------------------
__global__ void k_init(){
    int j = threadIdx.x;                 // 128 threads
    double a = (double)j * (3.14159265358979323846/64.0);
    float c = (float)cos(a), s = (float)sin(a);
    g_twF[2*j]   = pk2(c,c);  g_twF[2*j+1] = pk2(s,-s);
    g_twI[2*j]   = pk2(c,c);  g_twI[2*j+1] = pk2(-s,s);
}

// ---------------------------------------------------------------------------
// In-smem 128-point radix-2 DIF FFT with fused stage pairs (bit-identical to
// the sequential radix-2 version). xs[128 pts][64 cols] u64 packed complex.
// 512 threads: c = tid&63, tg = tid>>6 (8 groups x 4 quads per fused pass).
// On exit, slot i holds X[bitrev7(i)].
__device__ __forceinline__ void fft128(u64* xs, const ulonglong2* tws,
                                       int c, int tg){
    #pragma unroll 1
    for(int lm=6; lm>=2; lm-=2){
        int m = 1<<lm, hm = m>>1;
        #pragma unroll
        for(int u=0; u<4; u++){
            int q = tg*4+u;                 // 0..31 quads
            int j = q & (hm-1);
            int blk = q >> (lm-1);
            int i0 = blk*2*m + j;
            u64 a = xs[i0*64+c],       b = xs[(i0+hm)*64+c];
            u64 d = xs[(i0+m)*64+c],   e = xs[(i0+m+hm)*64+c];
            int eA = j<<(6-lm);
            ulonglong2 wA  = tws[eA];
            ulonglong2 wA2 = tws[eA+32];
            ulonglong2 wB  = tws[2*eA];
            u64 s0 = add2(a,d), d0 = fma2(d,NEG1C,a);
            u64 s1 = add2(b,e), d1 = fma2(e,NEG1C,b);
            u64 r0 = cmul2(d0, wA);
            u64 r1 = cmul2(d1, wA2);
            xs[i0*64+c]        = add2(s0,s1);
            xs[(i0+hm)*64+c]   = cmul2(fma2(s1,NEG1C,s0), wB);
            xs[(i0+m)*64+c]    = add2(r0,r1);
            xs[(i0+m+hm)*64+c] = cmul2(fma2(r1,NEG1C,r0), wB);
        }
        __syncthreads();
    }
    // final stage (m=1), twiddle = 1
    #pragma unroll
    for(int u=0; u<8; u++){
        int t = tg*8+u;                     // 0..63 pairs
        int i1 = 2*t;
        u64 a = xs[i1*64+c], b = xs[(i1+1)*64+c];
        xs[i1*64+c]     = add2(a,b);
        xs[(i1+1)*64+c] = fma2(b,NEG1C,a);
    }
    __syncthreads();
}

#define FFT_SMEM (65536 + 1024)

// ---------------------------------------------------------------------------
// Stage 1: rfft along W, two real channels packed per complex FFT.
// grid (B*H=512, 6 tiles of 128 channels), 512 thr.
__global__ void __launch_bounds__(512) k_s1(const float* __restrict__ x){
    extern __shared__ __align__(16) char smraw[];
    u64* xs = (u64*)smraw;                       // [128][64]
    ulonglong2* tws = (ulonglong2*)(smraw + 65536);
    int tid = threadIdx.x, c = tid&63, tg = tid>>6;
    int bh = blockIdx.x, cb = blockIdx.y*128;
    const float* xin = x + (size_t)bh*(WN*CN) + cb;
    for(int i=tid;i<8192;i+=512){
        int w=i>>6, cc=i&63;
        float2 v = *(const float2*)&xin[(size_t)w*CN + 2*cc];
        xs[i] = pk2(v.x, v.y);
    }
    if(tid<64) tws[tid] = *(const ulonglong2*)&g_twF[2*tid];
    __syncthreads();
    fft128(xs, tws, c, tg);

    // unscramble: Xc = (Z[k]+conj(Z[-k]))/2 ; Xd = -i(Z[k]-conj(Z[-k]))/2
    u64* ob = g_A + (size_t)bh*ROWST + cb;
    const float sc = 1.0f/256.0f;   // 0.5 * (1/128 ortho)
    for(int k=tg; k<65; k+=8){
        int s1 = __brev(k)>>25;
        int s2 = __brev((128-k)&127)>>25;
        u64 Z = xs[s1*64+c], Zm = xs[s2*64+c];
        float a,b,p,q; upk2(Z,a,b); upk2(Zm,p,q);
        ulonglong2 st;
        st.x = pk2(sc*(a+p), sc*(b-q));
        st.y = pk2(sc*(b+q), sc*(p-a));
        *(ulonglong2*)&ob[(size_t)k*CN + 2*c] = st;
    }
}

// ---------------------------------------------------------------------------
// Stage 2/4: complex FFT along H. dir=0: fwd g_A->g_B. dir=1: inv g_B->g_A.
// grid (B*65=260, 12 tiles of 64 channels), 512 thr.
__global__ void __launch_bounds__(512) k_ffth(int dir){
    extern __shared__ __align__(16) char smraw[];
    u64* xs = (u64*)smraw;
    ulonglong2* tws = (ulonglong2*)(smraw + 65536);
    int tid = threadIdx.x, c = tid&63, tg = tid>>6;
    int b = blockIdx.x / WFQ, wf = blockIdx.x % WFQ;
    int cb = blockIdx.y*64;
    const u64* in = dir ? g_B : g_A;
    u64* out      = dir ? g_A : g_B;
    size_t base = (size_t)b*HN*ROWST + (size_t)wf*CN + cb;

    for(int i=tid;i<4096;i+=512){
        int h=i>>5, cp=i&31;
        ulonglong2 v = *(const ulonglong2*)(in + base + (size_t)h*ROWST + 2*cp);
        *(ulonglong2*)&xs[h*64 + 2*cp] = v;
    }
    if(tid<64) tws[tid] = *(const ulonglong2*)(dir ? &g_twI[2*tid] : &g_twF[2*tid]);
    __syncthreads();
    fft128(xs, tws, c, tg);

    for(int s=tid;s<4096;s+=512){
        int islot=s>>5, cp=s&31;
        int k = __brev(islot)>>25;
        ulonglong2 v = *(const ulonglong2*)&xs[islot*64 + 2*cp];
        *(ulonglong2*)(out + base + (size_t)k*ROWST + 2*cp) = v;
    }
}

// ---------------------------------------------------------------------------
// Stage 3: one complex block-diagonal MLP layer with softshrink.
// (Best measured variant, R6: 515us.) x staged through smem in transposed
// [i][p] layout (coalesced LDG in, conflict-free LDS.128 out), two 48-i
// chunks, smem 87KB -> 2 CTAs/SM. Thread = 2 points x 6 output-pairs.
// grid (260 point-tiles of 128, 16 = 8 kb x 2 output-halves of 48). 256 thr
// = 64 point-lanes x 4 output-subgroups of 12.
#define MLP_XS    0
#define MLP_WR    49920
#define MLP_WI    68352
#define MLP_BS    86784
#define MLP_SMEM  87168
__global__ void __launch_bounds__(256,2) k_mlp(int which, const float* __restrict__ w,
                                               const float* __restrict__ bvec){
    extern __shared__ __align__(16) char smraw[];
    u64*    xs   = (u64*)(smraw + MLP_XS);       // [48 i][130 p]
    float*  wr_s = (float*)(smraw + MLP_WR);     // [96 i][48 o]
    float*  wi_s = (float*)(smraw + MLP_WI);
    float2* bs   = (float2*)(smraw + MLP_BS);
    int tid = threadIdx.x;
    int P0 = blockIdx.x*128;
    int kb = blockIdx.y & 7, o0 = (blockIdx.y>>3)*48;
    const u64* in = which ? g_A : g_B;
    u64* out      = which ? g_B : g_A;

    for(int t=tid;t<4608;t+=256){
        int i = t/48, oo = t - i*48;
        wr_s[t] = w[(size_t)kb*9216 + i*96 + o0 + oo];
        wi_s[t] = w[(size_t)(8+kb)*9216 + i*96 + o0 + oo];
    }
    if(tid<48) bs[tid] = make_float2(bvec[kb*96 + o0 + tid],
                                     bvec[768 + kb*96 + o0 + tid]);
    __syncthreads();

    int pl = tid&63, og = tid>>6, ob = og*12;
    u64 are[2][6], aim[2][6];
    #pragma unroll
    for(int k=0;k<6;k++){
        float2 b0 = bs[ob+2*k], b1 = bs[ob+2*k+1];
        u64 r = pk2(b0.x,b1.x), m = pk2(b0.y,b1.y);
        are[0][k]=r; aim[0][k]=m;
        are[1][k]=r; aim[1][k]=m;
    }

    #pragma unroll 1
    for(int ch=0; ch<2; ch++){
        if(ch) __syncthreads();   // prior chunk's reads done before overwrite
        // stage x chunk: [i 0..47][p 0..127], coalesced global reads
        for(int n=tid;n<6144;n+=256){
            int p = n/48, i = n - p*48;
            xs[i*130 + p] = in[(size_t)(P0+p)*CN + kb*96 + ch*48 + i];
        }
        __syncthreads();
        const float* wrb = wr_s + (ch*48)*48 + ob;
        const float* wib = wi_s + (ch*48)*48 + ob;
        #pragma unroll 2
        for(int i=0;i<48;i++){
            ulonglong2 xv = *(const ulonglong2*)&xs[i*130 + 2*pl];
            const ulonglong2* wrp = (const ulonglong2*)(wrb + i*48);
            const ulonglong2* wip = (const ulonglong2*)(wib + i*48);
            ulonglong2 wa = wrp[0], wb = wrp[1], wc = wrp[2];
            ulonglong2 va = wip[0], vb = wip[1], vc = wip[2];
            u64 wreg[6]; u64 vreg[6];
            wreg[0]=wa.x; wreg[1]=wa.y; wreg[2]=wb.x; wreg[3]=wb.y; wreg[4]=wc.x; wreg[5]=wc.y;
            vreg[0]=va.x; vreg[1]=va.y; vreg[2]=vb.x; vreg[3]=vb.y; vreg[4]=vc.x; vreg[5]=vc.y;
            #pragma unroll
            for(int t=0;t<2;t++){
                u64 xvt = t ? xv.y : xv.x;
                float xr,xi; upk2(xvt,xr,xi);
                u64 rr=pk2(xr,xr), iv=pk2(xi,xi), nii=pk2(-xi,-xi);
                #pragma unroll
                for(int k=0;k<6;k++){
                    are[t][k]=fma2(rr, wreg[k],are[t][k]);
                    are[t][k]=fma2(nii,vreg[k],are[t][k]);
                    aim[t][k]=fma2(iv, wreg[k],aim[t][k]);
                    aim[t][k]=fma2(rr, vreg[k],aim[t][k]);
                }
            }
        }
    }

    u64* obp = out + (size_t)(P0 + 2*pl)*CN + kb*96 + o0 + ob;
    #pragma unroll
    for(int t=0;t<2;t++){
        u64* op = obp + (size_t)t*CN;
        #pragma unroll
        for(int k=0;k<3;k++){
            float r0,r1,i0,i1,r2,r3,i2,i3;
            upk2(are[t][2*k],  r0,r1); upk2(aim[t][2*k],  i0,i1);
            upk2(are[t][2*k+1],r2,r3); upk2(aim[t][2*k+1],i2,i3);
            ulonglong2 s0, s1;
            s0.x = pk2(sshrink(r0), sshrink(i0));
            s0.y = pk2(sshrink(r1), sshrink(i1));
            s1.x = pk2(sshrink(r2), sshrink(i2));
            s1.y = pk2(sshrink(r3), sshrink(i3));
            *(ulonglong2*)(op + 4*k)     = s0;
            *(ulonglong2*)(op + 4*k + 2) = s1;
        }
    }
}

// ---------------------------------------------------------------------------
// Stage 5: irfft along W + residual, two real outputs packed per complex FFT.
// grid (512, 6 tiles of 128 channels), 512 thr.
__global__ void __launch_bounds__(512) k_s5(const float* __restrict__ x,
                                            float* __restrict__ y){
    extern __shared__ __align__(16) char smraw[];
    u64* xs = (u64*)smraw;
    ulonglong2* tws = (ulonglong2*)(smraw + 65536);
    int tid = threadIdx.x, c = tid&63, tg = tid>>6;
    int bh = blockIdx.x, cb = blockIdx.y*128;
    const u64* in = g_A + (size_t)bh*ROWST + cb;
    const float sc = 1.0f/128.0f;   // inverse ortho total

    // Build paired spectrum Z[k] = Xc[k] + i*Xd[k], hermitian-extended.
    // pocketfft C2R ignores Im at DC/Nyquist -> zero them.
    for(int t=tid;t<65*64;t+=512){
        int k=t>>6, cc=t&63;
        ulonglong2 v = *(const ulonglong2*)&in[(size_t)k*CN + 2*cc];
        float cr,ci,dr,di; upk2(v.x,cr,ci); upk2(v.y,dr,di);
        if(k==0 || k==64){ ci = 0.0f; di = 0.0f; }
        xs[k*64+cc] = pk2(sc*(cr-di), sc*(ci+dr));
        if(k>=1 && k<=63)
            xs[(128-k)*64+cc] = pk2(sc*(cr+di), sc*(dr-ci));
    }
    if(tid<64) tws[tid] = *(const ulonglong2*)&g_twI[2*tid];
    __syncthreads();
    fft128(xs, tws, c, tg);   // inverse (e^{+i}), unnormalized

    size_t obase = (size_t)bh*(WN*CN) + cb;
    for(int s=tid;s<8192;s+=512){
        int islot=s>>6, cc=s&63;
        int w = __brev(islot)>>25;
        float yr,yi; upk2(xs[s], yr, yi);
        size_t off = obase + (size_t)w*CN + 2*cc;
        float2 bv = *(const float2*)&x[off];
        *(float2*)&y[off] = make_float2(yr+bv.x, yi+bv.y);
    }
}

// ---------------------------------------------------------------------------
extern "C" void kernel_launch(void* const* d_in, const int* in_sizes, int n_in,
                              void* d_out, int out_size) {
    const float* x  = (const float*)d_in[0];
    const float* w1 = (const float*)d_in[1];
    const float* w2 = (const float*)d_in[2];
    const float* b1 = (const float*)d_in[3];
    const float* b2 = (const float*)d_in[4];
    float* y = (float*)d_out;

    cudaFuncSetAttribute(k_s1,   cudaFuncAttributeMaxDynamicSharedMemorySize, FFT_SMEM);
    cudaFuncSetAttribute(k_ffth, cudaFuncAttributeMaxDynamicSharedMemorySize, FFT_SMEM);
    cudaFuncSetAttribute(k_s5,   cudaFuncAttributeMaxDynamicSharedMemorySize, FFT_SMEM);
    cudaFuncSetAttribute(k_mlp,  cudaFuncAttributeMaxDynamicSharedMemorySize, MLP_SMEM);

    k_init<<<1,128>>>();
    k_s1  <<<dim3(512,6), 512, FFT_SMEM>>>(x);
    k_ffth<<<dim3(260,12),512, FFT_SMEM>>>(0);
    k_mlp <<<dim3(260,16),256, MLP_SMEM>>>(0, w1, b1);
    k_mlp <<<dim3(260,16),256, MLP_SMEM>>>(1, w2, b2);
    k_ffth<<<dim3(260,12),512, FFT_SMEM>>>(1);
    k_s5  <<<dim3(512,6), 512, FFT_SMEM>>>(x, y);
    (void)in_sizes; (void)n_in; (void)out_size;
}

// round 11
// speedup vs baseline: 3.0060x; 1.0907x over previous
#include <cuda_runtime.h>
#include <math.h>

typedef unsigned long long u64;
typedef unsigned int u32;

#define BN 4
#define HN 128
#define WN 128
#define CN 768
#define WFQ 65
#define ROWST (WFQ*CN)              /* 49920 u64 per (b,h) row */
#define NELEM (BN*HN*WFQ*CN)        /* 25,559,040 complex */

// Scratch complex buffers (re = low 32 bits, im = high 32 bits)
__device__ __align__(128) u64 g_A[NELEM];
__device__ __align__(128) u64 g_B[NELEM];
// Twiddle tables (128th roots of unity), cmul-ready pairs
__device__ __align__(16) u64 g_twF[256];   // pairs (c,c),(s,-s)   fwd  e^{-i}
__device__ __align__(16) u64 g_twI[256];   // pairs (c,c),(-s,s)   inv  e^{+i}

__device__ __forceinline__ u64 pk2(float lo, float hi){
    u64 r; asm("mov.b64 %0,{%1,%2};":"=l"(r):"f"(lo),"f"(hi)); return r;
}
__device__ __forceinline__ void upk2(u64 v, float& lo, float& hi){
    asm("mov.b64 {%0,%1},%2;":"=f"(lo),"=f"(hi):"l"(v));
}
__device__ __forceinline__ u64 fma2(u64 a, u64 b, u64 c){
    u64 d; asm("fma.rn.f32x2 %0,%1,%2,%3;":"=l"(d):"l"(a),"l"(b),"l"(c)); return d;
}
__device__ __forceinline__ u64 mul2(u64 a, u64 b){
    u64 d; asm("mul.rn.f32x2 %0,%1,%2;":"=l"(d):"l"(a),"l"(b)); return d;
}
__device__ __forceinline__ u64 add2(u64 a, u64 b){
    u64 d; asm("add.rn.f32x2 %0,%1,%2;":"=l"(d):"l"(a),"l"(b)); return d;
}
__device__ __forceinline__ u64 swp2(u64 v){
    float lo,hi; upk2(v,lo,hi); return pk2(hi,lo);
}
__device__ __forceinline__ float sshrink(float v){
    return copysignf(fmaxf(fabsf(v)-0.01f,0.0f), v);
}
__device__ __forceinline__ u32 smem_u32(const void* p){
    u32 a; asm("{ .reg .u64 t; cvta.to.shared.u64 t, %1; cvt.u32.u64 %0, t; }"
               : "=r"(a) : "l"(p)); return a;
}
__device__ __forceinline__ void cpa8(u32 saddr, const void* g){
    asm volatile("cp.async.ca.shared.global [%0], [%1], 8;"
                 :: "r"(saddr), "l"(g) : "memory");
}
#define CPA_COMMIT() asm volatile("cp.async.commit_group;":::"memory")
#define CPA_WAIT(n)  asm volatile("cp.async.wait_group %0;"::"n"(n):"memory")

#define NEG1C 0xBF800000BF800000ULL  /* (-1.f,-1.f) */

__device__ __forceinline__ u64 cmul2(u64 v, ulonglong2 w){
    return fma2(swp2(v), w.y, mul2(v, w.x));
}

// ---------------------------------------------------------------------------
__global__ void k_init(){
    int j = threadIdx.x;                 // 128 threads
    double a = (double)j * (3.14159265358979323846/64.0);
    float c = (float)cos(a), s = (float)sin(a);
    g_twF[2*j]   = pk2(c,c);  g_twF[2*j+1] = pk2(s,-s);
    g_twI[2*j]   = pk2(c,c);  g_twI[2*j+1] = pk2(-s,s);
}

// ---------------------------------------------------------------------------
// In-smem 128-point radix-2 DIF FFT with fused stage pairs (bit-identical to
// the sequential radix-2 version). xs[128 pts][64 cols] u64 packed complex.
// 512 threads: c = tid&63, tg = tid>>6 (8 groups x 4 quads per fused pass).
__device__ __forceinline__ void fft128(u64* xs, const ulonglong2* tws,
                                       int c, int tg){
    #pragma unroll 1
    for(int lm=6; lm>=2; lm-=2){
        int m = 1<<lm, hm = m>>1;
        #pragma unroll
        for(int u=0; u<4; u++){
            int q = tg*4+u;                 // 0..31 quads
            int j = q & (hm-1);
            int blk = q >> (lm-1);
            int i0 = blk*2*m + j;
            u64 a = xs[i0*64+c],       b = xs[(i0+hm)*64+c];
            u64 d = xs[(i0+m)*64+c],   e = xs[(i0+m+hm)*64+c];
            int eA = j<<(6-lm);
            ulonglong2 wA  = tws[eA];
            ulonglong2 wA2 = tws[eA+32];
            ulonglong2 wB  = tws[2*eA];
            u64 s0 = add2(a,d), d0 = fma2(d,NEG1C,a);
            u64 s1 = add2(b,e), d1 = fma2(e,NEG1C,b);
            u64 r0 = cmul2(d0, wA);
            u64 r1 = cmul2(d1, wA2);
            xs[i0*64+c]        = add2(s0,s1);
            xs[(i0+hm)*64+c]   = cmul2(fma2(s1,NEG1C,s0), wB);
            xs[(i0+m)*64+c]    = add2(r0,r1);
            xs[(i0+m+hm)*64+c] = cmul2(fma2(r1,NEG1C,r0), wB);
        }
        __syncthreads();
    }
    // final stage (m=1), twiddle = 1
    #pragma unroll
    for(int u=0; u<8; u++){
        int t = tg*8+u;                     // 0..63 pairs
        int i1 = 2*t;
        u64 a = xs[i1*64+c], b = xs[(i1+1)*64+c];
        xs[i1*64+c]     = add2(a,b);
        xs[(i1+1)*64+c] = fma2(b,NEG1C,a);
    }
    __syncthreads();
}

#define FFT_SMEM (65536 + 1024)

// ---------------------------------------------------------------------------
// Stage 1: rfft along W, two real channels packed per complex FFT.
__global__ void __launch_bounds__(512) k_s1(const float* __restrict__ x){
    extern __shared__ __align__(16) char smraw[];
    u64* xs = (u64*)smraw;                       // [128][64]
    ulonglong2* tws = (ulonglong2*)(smraw + 65536);
    int tid = threadIdx.x, c = tid&63, tg = tid>>6;
    int bh = blockIdx.x, cb = blockIdx.y*128;
    const float* xin = x + (size_t)bh*(WN*CN) + cb;
    for(int i=tid;i<8192;i+=512){
        int w=i>>6, cc=i&63;
        float2 v = *(const float2*)&xin[(size_t)w*CN + 2*cc];
        xs[i] = pk2(v.x, v.y);
    }
    if(tid<64) tws[tid] = *(const ulonglong2*)&g_twF[2*tid];
    __syncthreads();
    fft128(xs, tws, c, tg);

    // unscramble: Xc = (Z[k]+conj(Z[-k]))/2 ; Xd = -i(Z[k]-conj(Z[-k]))/2
    u64* ob = g_A + (size_t)bh*ROWST + cb;
    const float sc = 1.0f/256.0f;   // 0.5 * (1/128 ortho)
    for(int k=tg; k<65; k+=8){
        int s1 = __brev(k)>>25;
        int s2 = __brev((128-k)&127)>>25;
        u64 Z = xs[s1*64+c], Zm = xs[s2*64+c];
        float a,b,p,q; upk2(Z,a,b); upk2(Zm,p,q);
        ulonglong2 st;
        st.x = pk2(sc*(a+p), sc*(b-q));
        st.y = pk2(sc*(b+q), sc*(p-a));
        *(ulonglong2*)&ob[(size_t)k*CN + 2*c] = st;
    }
}

// ---------------------------------------------------------------------------
// Stage 2/4: complex FFT along H. dir=0: fwd g_A->g_B. dir=1: inv g_B->g_A.
__global__ void __launch_bounds__(512) k_ffth(int dir){
    extern __shared__ __align__(16) char smraw[];
    u64* xs = (u64*)smraw;
    ulonglong2* tws = (ulonglong2*)(smraw + 65536);
    int tid = threadIdx.x, c = tid&63, tg = tid>>6;
    int b = blockIdx.x / WFQ, wf = blockIdx.x % WFQ;
    int cb = blockIdx.y*64;
    const u64* in = dir ? g_B : g_A;
    u64* out      = dir ? g_A : g_B;
    size_t base = (size_t)b*HN*ROWST + (size_t)wf*CN + cb;

    for(int i=tid;i<4096;i+=512){
        int h=i>>5, cp=i&31;
        ulonglong2 v = *(const ulonglong2*)(in + base + (size_t)h*ROWST + 2*cp);
        *(ulonglong2*)&xs[h*64 + 2*cp] = v;
    }
    if(tid<64) tws[tid] = *(const ulonglong2*)(dir ? &g_twI[2*tid] : &g_twF[2*tid]);
    __syncthreads();
    fft128(xs, tws, c, tg);

    for(int s=tid;s<4096;s+=512){
        int islot=s>>5, cp=s&31;
        int k = __brev(islot)>>25;
        ulonglong2 v = *(const ulonglong2*)&xs[islot*64 + 2*cp];
        *(ulonglong2*)(out + base + (size_t)k*ROWST + 2*cp) = v;
    }
}

// ---------------------------------------------------------------------------
// Stage 3: one complex block-diagonal MLP layer with softshrink.
// R6 compute structure + cp.async DOUBLE-BUFFERED x staging: three 32-i
// chunks, prefetch ch+1 while computing ch. smem ~102KB -> 2 CTAs/SM.
// Thread = 2 points x 6 output-pairs.
// grid (260 point-tiles of 128, 16 = 8 kb x 2 output-halves of 48). 256 thr.
#define MLP_XS0   0
#define MLP_XS1   33280
#define MLP_WR    66560
#define MLP_WI    84992
#define MLP_BS    103424
#define MLP_SMEM  103936
__global__ void __launch_bounds__(256,2) k_mlp(int which, const float* __restrict__ w,
                                               const float* __restrict__ bvec){
    extern __shared__ __align__(16) char smraw[];
    u64*    xbuf[2];
    xbuf[0] = (u64*)(smraw + MLP_XS0);           // [32 i][130 p]
    xbuf[1] = (u64*)(smraw + MLP_XS1);
    float*  wr_s = (float*)(smraw + MLP_WR);     // [96 i][48 o]
    float*  wi_s = (float*)(smraw + MLP_WI);
    float2* bs   = (float2*)(smraw + MLP_BS);
    u32 smb = smem_u32(smraw);
    int tid = threadIdx.x;
    int P0 = blockIdx.x*128;
    int kb = blockIdx.y & 7, o0 = (blockIdx.y>>3)*48;
    const u64* in = which ? g_A : g_B;
    u64* out      = which ? g_B : g_A;
    const u64* inb = in + (size_t)P0*CN + kb*96;

    // prefetch chunk 0
    for(int n=tid;n<4096;n+=256){
        int p = n>>5, i = n&31;
        cpa8(smb + MLP_XS0 + (u32)(i*130+p)*8, inb + (size_t)p*CN + i);
    }
    CPA_COMMIT();

    for(int t=tid;t<4608;t+=256){
        int i = t/48, oo = t - i*48;
        wr_s[t] = w[(size_t)kb*9216 + i*96 + o0 + oo];
        wi_s[t] = w[(size_t)(8+kb)*9216 + i*96 + o0 + oo];
    }
    if(tid<48) bs[tid] = make_float2(bvec[kb*96 + o0 + tid],
                                     bvec[768 + kb*96 + o0 + tid]);
    __syncthreads();     // weights+bias visible

    int pl = tid&63, og = tid>>6, ob = og*12;
    u64 are[2][6], aim[2][6];
    #pragma unroll
    for(int k=0;k<6;k++){
        float2 b0 = bs[ob+2*k], b1 = bs[ob+2*k+1];
        u64 r = pk2(b0.x,b1.x), m = pk2(b0.y,b1.y);
        are[0][k]=r; aim[0][k]=m;
        are[1][k]=r; aim[1][k]=m;
    }

    #pragma unroll 1
    for(int ch=0; ch<3; ch++){
        // prefetch next chunk into the other buffer (overlaps compute below)
        if(ch<2){
            u32 dst = smb + ((ch+1)&1 ? MLP_XS1 : MLP_XS0);
            const u64* src = inb + (ch+1)*32;
            for(int n=tid;n<4096;n+=256){
                int p = n>>5, i = n&31;
                cpa8(dst + (u32)(i*130+p)*8, src + (size_t)p*CN + i);
            }
            CPA_COMMIT();
            CPA_WAIT(1);          // chunk ch landed
        } else {
            CPA_WAIT(0);
        }
        __syncthreads();

        const u64* xsb = xbuf[ch&1];
        const float* wrb = wr_s + (ch*32)*48 + ob;
        const float* wib = wi_s + (ch*32)*48 + ob;
        #pragma unroll 2
        for(int i=0;i<32;i++){
            ulonglong2 xv = *(const ulonglong2*)&xsb[i*130 + 2*pl];
            const ulonglong2* wrp = (const ulonglong2*)(wrb + i*48);
            const ulonglong2* wip = (const ulonglong2*)(wib + i*48);
            ulonglong2 wa = wrp[0], wb = wrp[1], wc = wrp[2];
            ulonglong2 va = wip[0], vb = wip[1], vc = wip[2];
            u64 wreg[6]; u64 vreg[6];
            wreg[0]=wa.x; wreg[1]=wa.y; wreg[2]=wb.x; wreg[3]=wb.y; wreg[4]=wc.x; wreg[5]=wc.y;
            vreg[0]=va.x; vreg[1]=va.y; vreg[2]=vb.x; vreg[3]=vb.y; vreg[4]=vc.x; vreg[5]=vc.y;
            #pragma unroll
            for(int t=0;t<2;t++){
                u64 xvt = t ? xv.y : xv.x;
                float xr,xi; upk2(xvt,xr,xi);
                u64 rr=pk2(xr,xr), iv=pk2(xi,xi), nii=pk2(-xi,-xi);
                #pragma unroll
                for(int k=0;k<6;k++){
                    are[t][k]=fma2(rr, wreg[k],are[t][k]);
                    are[t][k]=fma2(nii,vreg[k],are[t][k]);
                    aim[t][k]=fma2(iv, wreg[k],aim[t][k]);
                    aim[t][k]=fma2(rr, vreg[k],aim[t][k]);
                }
            }
        }
        __syncthreads();   // compute(ch) done before buffer reuse next iter
    }

    u64* obp = out + (size_t)(P0 + 2*pl)*CN + kb*96 + o0 + ob;
    #pragma unroll
    for(int t=0;t<2;t++){
        u64* op = obp + (size_t)t*CN;
        #pragma unroll
        for(int k=0;k<3;k++){
            float r0,r1,i0,i1,r2,r3,i2,i3;
            upk2(are[t][2*k],  r0,r1); upk2(aim[t][2*k],  i0,i1);
            upk2(are[t][2*k+1],r2,r3); upk2(aim[t][2*k+1],i2,i3);
            ulonglong2 s0, s1;
            s0.x = pk2(sshrink(r0), sshrink(i0));
            s0.y = pk2(sshrink(r1), sshrink(i1));
            s1.x = pk2(sshrink(r2), sshrink(i2));
            s1.y = pk2(sshrink(r3), sshrink(i3));
            *(ulonglong2*)(op + 4*k)     = s0;
            *(ulonglong2*)(op + 4*k + 2) = s1;
        }
    }
}

// ---------------------------------------------------------------------------
// Stage 5: irfft along W + residual, two real outputs packed per complex FFT.
__global__ void __launch_bounds__(512) k_s5(const float* __restrict__ x,
                                            float* __restrict__ y){
    extern __shared__ __align__(16) char smraw[];
    u64* xs = (u64*)smraw;
    ulonglong2* tws = (ulonglong2*)(smraw + 65536);
    int tid = threadIdx.x, c = tid&63, tg = tid>>6;
    int bh = blockIdx.x, cb = blockIdx.y*128;
    const u64* in = g_A + (size_t)bh*ROWST + cb;
    const float sc = 1.0f/128.0f;   // inverse ortho total

    // Build paired spectrum Z[k] = Xc[k] + i*Xd[k], hermitian-extended.
    // pocketfft C2R ignores Im at DC/Nyquist -> zero them.
    for(int t=tid;t<65*64;t+=512){
        int k=t>>6, cc=t&63;
        ulonglong2 v = *(const ulonglong2*)&in[(size_t)k*CN + 2*cc];
        float cr,ci,dr,di; upk2(v.x,cr,ci); upk2(v.y,dr,di);
        if(k==0 || k==64){ ci = 0.0f; di = 0.0f; }
        xs[k*64+cc] = pk2(sc*(cr-di), sc*(ci+dr));
        if(k>=1 && k<=63)
            xs[(128-k)*64+cc] = pk2(sc*(cr+di), sc*(dr-ci));
    }
    if(tid<64) tws[tid] = *(const ulonglong2*)&g_twI[2*tid];
    __syncthreads();
    fft128(xs, tws, c, tg);   // inverse (e^{+i}), unnormalized

    size_t obase = (size_t)bh*(WN*CN) + cb;
    for(int s=tid;s<8192;s+=512){
        int islot=s>>6, cc=s&63;
        int w = __brev(islot)>>25;
        float yr,yi; upk2(xs[s], yr, yi);
        size_t off = obase + (size_t)w*CN + 2*cc;
        float2 bv = *(const float2*)&x[off];
        *(float2*)&y[off] = make_float2(yr+bv.x, yi+bv.y);
    }
}

// ---------------------------------------------------------------------------
extern "C" void kernel_launch(void* const* d_in, const int* in_sizes, int n_in,
                              void* d_out, int out_size) {
    const float* x  = (const float*)d_in[0];
    const float* w1 = (const float*)d_in[1];
    const float* w2 = (const float*)d_in[2];
    const float* b1 = (const float*)d_in[3];
    const float* b2 = (const float*)d_in[4];
    float* y = (float*)d_out;

    cudaFuncSetAttribute(k_s1,   cudaFuncAttributeMaxDynamicSharedMemorySize, FFT_SMEM);
    cudaFuncSetAttribute(k_ffth, cudaFuncAttributeMaxDynamicSharedMemorySize, FFT_SMEM);
    cudaFuncSetAttribute(k_s5,   cudaFuncAttributeMaxDynamicSharedMemorySize, FFT_SMEM);
    cudaFuncSetAttribute(k_mlp,  cudaFuncAttributeMaxDynamicSharedMemorySize, MLP_SMEM);

    k_init<<<1,128>>>();
    k_s1  <<<dim3(512,6), 512, FFT_SMEM>>>(x);
    k_ffth<<<dim3(260,12),512, FFT_SMEM>>>(0);
    k_mlp <<<dim3(260,16),256, MLP_SMEM>>>(0, w1, b1);
    k_mlp <<<dim3(260,16),256, MLP_SMEM>>>(1, w2, b2);
    k_ffth<<<dim3(260,12),512, FFT_SMEM>>>(1);
    k_s5  <<<dim3(512,6), 512, FFT_SMEM>>>(x, y);
    (void)in_sizes; (void)n_in; (void)out_size;
}